// round 1
// baseline (speedup 1.0000x reference)
#include <cuda_runtime.h>
#include <math.h>

// Problem constants (fixed by the reference)
#define L_SEQ 2048
#define DM    1024
#define NH    16
#define HD    64
#define BH    32           // B * NH
#define NEMB  1025
#define MROWS 4096         // B * L

// ---------------- device scratch (allocation-free rule: __device__ globals) ----
__device__ float g_Q[BH * L_SEQ * HD];          // 16.8 MB, head-split (bh, l, d)
__device__ float g_K[BH * L_SEQ * HD];
__device__ float g_V[BH * L_SEQ * HD];
__device__ float g_attn[MROWS * DM];            // 16.8 MB, (b*L+l, h*64+d)
__device__ float g_qrel[67174400];              // BH*L_SEQ*NEMB = 268.7 MB

// =====================================================================
// SGEMM: C = A(MxK) @ W(KxN) + bias, optional head-split output remap.
// 128x128 block tile, BK=16, 256 threads, 8x8 micro-tile.
// =====================================================================
__global__ void __launch_bounds__(256) sgemm_kernel(
    const float* __restrict__ A, const float* __restrict__ W,
    const float* __restrict__ bias, float* __restrict__ C,
    int M, int N, int K, int headsplit)
{
    __shared__ float As[16][132];   // transposed A tile, padded
    __shared__ float Bs[16][128];

    const int tid = threadIdx.x;
    const int bm = blockIdx.y * 128;
    const int bn = blockIdx.x * 128;
    const int tx = tid & 15;
    const int ty = tid >> 4;
    const int ar = tid >> 2;          // 0..63
    const int ac = (tid & 3) << 2;    // 0,4,8,12
    const int br = tid >> 5;          // 0..7
    const int bc = (tid & 31) << 2;   // 0..124

    float acc[8][8];
#pragma unroll
    for (int i = 0; i < 8; i++)
#pragma unroll
        for (int j = 0; j < 8; j++) acc[i][j] = 0.f;

    for (int k0 = 0; k0 < K; k0 += 16) {
#pragma unroll
        for (int rr = 0; rr < 2; rr++) {
            float4 a4 = *(const float4*)(A + (size_t)(bm + ar + rr * 64) * K + k0 + ac);
            As[ac + 0][ar + rr * 64] = a4.x;
            As[ac + 1][ar + rr * 64] = a4.y;
            As[ac + 2][ar + rr * 64] = a4.z;
            As[ac + 3][ar + rr * 64] = a4.w;
        }
#pragma unroll
        for (int rr = 0; rr < 2; rr++) {
            *(float4*)(&Bs[br + rr * 8][bc]) =
                *(const float4*)(W + (size_t)(k0 + br + rr * 8) * N + bn + bc);
        }
        __syncthreads();
#pragma unroll
        for (int kk = 0; kk < 16; kk++) {
            float a[8], b[8];
            *(float4*)(a)     = *(float4*)(&As[kk][ty * 8]);
            *(float4*)(a + 4) = *(float4*)(&As[kk][ty * 8 + 4]);
            *(float4*)(b)     = *(float4*)(&Bs[kk][tx * 8]);
            *(float4*)(b + 4) = *(float4*)(&Bs[kk][tx * 8 + 4]);
#pragma unroll
            for (int i = 0; i < 8; i++)
#pragma unroll
                for (int j = 0; j < 8; j++)
                    acc[i][j] = fmaf(a[i], b[j], acc[i][j]);
        }
        __syncthreads();
    }

#pragma unroll
    for (int i = 0; i < 8; i++) {
        const int row = bm + ty * 8 + i;
#pragma unroll
        for (int j = 0; j < 8; j++) {
            const int col = bn + tx * 8 + j;
            const float v = acc[i][j] + bias[col];
            if (headsplit) {
                const int bb = row >> 11;      // L=2048
                const int l  = row & 2047;
                const int h  = col >> 6;       // HD=64
                const int d  = col & 63;
                C[(((size_t)(bb * NH + h)) * L_SEQ + l) * HD + d] = v;
            } else {
                C[(size_t)row * N + col] = v;
            }
        }
    }
}

// =====================================================================
// q_rel = Qh(65536 x 64) @ rel_emb^T (64 x 1025)
// 64x64 block, full K=64 in smem, 256 threads, 4x4 micro.
// =====================================================================
__global__ void __launch_bounds__(256) qrel_kernel(const float* __restrict__ E)
{
    __shared__ float sQ[64][65];
    __shared__ float sE[64][65];

    const int tid = threadIdx.x;
    const int r0 = blockIdx.y << 6;
    const int n0 = blockIdx.x << 6;
    const int tx = tid & 15, ty = tid >> 4;
    const int tx4 = tx << 2, ty4 = ty << 2;

    for (int idx = tid; idx < 1024; idx += 256) {
        const int r = idx >> 4;
        const int c = (idx & 15) << 2;
        float4 q4 = *(const float4*)(g_Q + (size_t)(r0 + r) * 64 + c);
        sQ[r][c] = q4.x; sQ[r][c + 1] = q4.y; sQ[r][c + 2] = q4.z; sQ[r][c + 3] = q4.w;
        const int er = n0 + r;
        float4 e4 = make_float4(0.f, 0.f, 0.f, 0.f);
        if (er < NEMB) e4 = *(const float4*)(E + (size_t)er * 64 + c);
        sE[r][c] = e4.x; sE[r][c + 1] = e4.y; sE[r][c + 2] = e4.z; sE[r][c + 3] = e4.w;
    }
    __syncthreads();

    float acc[4][4];
#pragma unroll
    for (int i = 0; i < 4; i++)
#pragma unroll
        for (int j = 0; j < 4; j++) acc[i][j] = 0.f;

#pragma unroll 8
    for (int k = 0; k < 64; k++) {
        float a[4], b[4];
#pragma unroll
        for (int i = 0; i < 4; i++) a[i] = sQ[ty4 + i][k];
#pragma unroll
        for (int j = 0; j < 4; j++) b[j] = sE[tx4 + j][k];
#pragma unroll
        for (int i = 0; i < 4; i++)
#pragma unroll
            for (int j = 0; j < 4; j++)
                acc[i][j] = fmaf(a[i], b[j], acc[i][j]);
    }

#pragma unroll
    for (int i = 0; i < 4; i++) {
        const size_t row = (size_t)(r0 + ty4 + i);
#pragma unroll
        for (int j = 0; j < 4; j++) {
            const int n = n0 + tx4 + j;
            if (n < NEMB) g_qrel[row * NEMB + n] = acc[i][j];
        }
    }
}

// =====================================================================
// Flash attention per (bh, 64-row i tile). Streams 64-wide K/V tiles,
// online softmax in exp2 domain, positional term gathered from g_qrel.
// Writes to g_attn in (b*L+l, h*64+d) layout for the final GEMM.
// =====================================================================
__global__ void __launch_bounds__(256) flash_kernel()
{
    extern __shared__ float sm[];
    float* sQ = sm;                  // [64][65]
    float* sK = sm + 64 * 65;        // [64][65] (reused as P)
    float* sV = sm + 2 * 64 * 65;    // [64][64]

    const int tid = threadIdx.x;
    const int tx = tid & 15, ty = tid >> 4;
    const int tx4 = tx << 2, ty4 = ty << 2;
    const int bh = blockIdx.y;
    const int i0 = blockIdx.x << 6;

    const float* Qb = g_Q + (size_t)bh * L_SEQ * HD;
    const float* Kb = g_K + (size_t)bh * L_SEQ * HD;
    const float* Vb = g_V + (size_t)bh * L_SEQ * HD;

    for (int idx = tid; idx < 1024; idx += 256) {
        const int r = idx >> 4;
        const int c = (idx & 15) << 2;
        float4 q4 = *(const float4*)(Qb + (size_t)(i0 + r) * 64 + c);
        sQ[r * 65 + c]     = q4.x;
        sQ[r * 65 + c + 1] = q4.y;
        sQ[r * 65 + c + 2] = q4.z;
        sQ[r * 65 + c + 3] = q4.w;
    }

    float m_s[4], l_s[4], o[4][4];
#pragma unroll
    for (int i = 0; i < 4; i++) {
        m_s[i] = -1e30f;
        l_s[i] = 0.f;
#pragma unroll
        for (int j = 0; j < 4; j++) o[i][j] = 0.f;
    }

    const float SCL = 0.125f * 1.4426950408889634f;  // (1/sqrt(64)) * log2(e)
    const float* qr[4];
#pragma unroll
    for (int i = 0; i < 4; i++)
        qr[i] = g_qrel + (size_t)(bh * L_SEQ + i0 + ty4 + i) * NEMB + 512;

    for (int j0 = 0; j0 < L_SEQ; j0 += 64) {
        __syncthreads();   // previous iteration done with sK/sV (also covers sQ on iter 0)
        for (int idx = tid; idx < 1024; idx += 256) {
            const int r = idx >> 4;
            const int c = (idx & 15) << 2;
            float4 k4 = *(const float4*)(Kb + (size_t)(j0 + r) * 64 + c);
            sK[r * 65 + c]     = k4.x;
            sK[r * 65 + c + 1] = k4.y;
            sK[r * 65 + c + 2] = k4.z;
            sK[r * 65 + c + 3] = k4.w;
            *(float4*)(sV + r * 64 + c) = *(const float4*)(Vb + (size_t)(j0 + r) * 64 + c);
        }
        __syncthreads();

        // S = Q @ K^T   (64x64 tile, 4x4 per thread)
        float s[4][4];
#pragma unroll
        for (int i = 0; i < 4; i++)
#pragma unroll
            for (int j = 0; j < 4; j++) s[i][j] = 0.f;
#pragma unroll 8
        for (int k = 0; k < 64; k++) {
            float a[4], b[4];
#pragma unroll
            for (int i = 0; i < 4; i++) a[i] = sQ[(ty4 + i) * 65 + k];
#pragma unroll
            for (int j = 0; j < 4; j++) b[j] = sK[(tx4 + j) * 65 + k];
#pragma unroll
            for (int i = 0; i < 4; i++)
#pragma unroll
                for (int j = 0; j < 4; j++)
                    s[i][j] = fmaf(a[i], b[j], s[i][j]);
        }

        // + relative-position term, scale into exp2 domain
#pragma unroll
        for (int i = 0; i < 4; i++) {
            const int ig = i0 + ty4 + i;
#pragma unroll
            for (int j = 0; j < 4; j++) {
                int rel = j0 + tx4 + j - ig;
                rel = max(-512, min(512, rel));
                s[i][j] = (s[i][j] + qr[i][rel]) * SCL;
            }
        }

        // online softmax (rows split across 16 lanes: shfl_xor widths 8..1)
#pragma unroll
        for (int i = 0; i < 4; i++) {
            float mt = fmaxf(fmaxf(s[i][0], s[i][1]), fmaxf(s[i][2], s[i][3]));
            mt = fmaxf(mt, __shfl_xor_sync(0xffffffffu, mt, 8));
            mt = fmaxf(mt, __shfl_xor_sync(0xffffffffu, mt, 4));
            mt = fmaxf(mt, __shfl_xor_sync(0xffffffffu, mt, 2));
            mt = fmaxf(mt, __shfl_xor_sync(0xffffffffu, mt, 1));
            const float mnew = fmaxf(m_s[i], mt);
            const float corr = exp2f(m_s[i] - mnew);
            m_s[i] = mnew;
            float rs = 0.f;
#pragma unroll
            for (int j = 0; j < 4; j++) {
                const float p = exp2f(s[i][j] - mnew);
                s[i][j] = p;
                rs += p;
            }
            rs += __shfl_xor_sync(0xffffffffu, rs, 8);
            rs += __shfl_xor_sync(0xffffffffu, rs, 4);
            rs += __shfl_xor_sync(0xffffffffu, rs, 2);
            rs += __shfl_xor_sync(0xffffffffu, rs, 1);
            l_s[i] = l_s[i] * corr + rs;
#pragma unroll
            for (int j = 0; j < 4; j++) o[i][j] *= corr;
        }

        __syncthreads();   // everyone done reading sK as K
#pragma unroll
        for (int i = 0; i < 4; i++)
#pragma unroll
            for (int j = 0; j < 4; j++)
                sK[(ty4 + i) * 65 + tx4 + j] = s[i][j];   // P tile
        __syncthreads();

        // O += P @ V
#pragma unroll 8
        for (int k = 0; k < 64; k++) {
            float p[4];
#pragma unroll
            for (int i = 0; i < 4; i++) p[i] = sK[(ty4 + i) * 65 + k];
            const float4 v4 = *(const float4*)(sV + k * 64 + tx4);
#pragma unroll
            for (int i = 0; i < 4; i++) {
                o[i][0] = fmaf(p[i], v4.x, o[i][0]);
                o[i][1] = fmaf(p[i], v4.y, o[i][1]);
                o[i][2] = fmaf(p[i], v4.z, o[i][2]);
                o[i][3] = fmaf(p[i], v4.w, o[i][3]);
            }
        }
    }

    // normalize + write merged-head layout
    const int bb = bh >> 4;
    const int h  = bh & 15;
#pragma unroll
    for (int i = 0; i < 4; i++) {
        const float inv = 1.f / l_s[i];
        const size_t row = (size_t)(bb * L_SEQ + i0 + ty4 + i);
        float4 val = make_float4(o[i][0] * inv, o[i][1] * inv, o[i][2] * inv, o[i][3] * inv);
        *(float4*)(g_attn + row * DM + h * 64 + tx4) = val;
    }
}

// =====================================================================
extern "C" void kernel_launch(void* const* d_in, const int* in_sizes, int n_in,
                              void* d_out, int out_size)
{
    const float* query = (const float*)d_in[0];
    const float* key   = (const float*)d_in[1];
    const float* value = (const float*)d_in[2];
    const float* wq    = (const float*)d_in[3];
    const float* bq    = (const float*)d_in[4];
    const float* wk    = (const float*)d_in[5];
    const float* bk    = (const float*)d_in[6];
    const float* wv    = (const float*)d_in[7];
    const float* bv    = (const float*)d_in[8];
    const float* wo    = (const float*)d_in[9];
    const float* bo    = (const float*)d_in[10];
    const float* rel   = (const float*)d_in[11];

    float *pQ, *pK, *pV, *pAttn;
    cudaGetSymbolAddress((void**)&pQ, g_Q);
    cudaGetSymbolAddress((void**)&pK, g_K);
    cudaGetSymbolAddress((void**)&pV, g_V);
    cudaGetSymbolAddress((void**)&pAttn, g_attn);

    const dim3 gproj(8, 32);   // N/128, M/128
    sgemm_kernel<<<gproj, 256>>>(query, wq, bq, pQ, MROWS, DM, DM, 1);
    sgemm_kernel<<<gproj, 256>>>(key,   wk, bk, pK, MROWS, DM, DM, 1);
    sgemm_kernel<<<gproj, 256>>>(value, wv, bv, pV, MROWS, DM, DM, 1);

    qrel_kernel<<<dim3(17, 1024), 256>>>(rel);

    const int smem = (64 * 65 * 2 + 64 * 64) * (int)sizeof(float);  // 49664 B
    cudaFuncSetAttribute(flash_kernel, cudaFuncAttributeMaxDynamicSharedMemorySize, smem);
    flash_kernel<<<dim3(32, 32), 256, smem>>>();

    sgemm_kernel<<<gproj, 256>>>(pAttn, wo, bo, (float*)d_out, MROWS, DM, DM, 0);
}

// round 3
// speedup vs baseline: 1.6048x; 1.6048x over previous
#include <cuda_runtime.h>
#include <cuda_bf16.h>
#include <stdint.h>
#include <math.h>

// Problem constants
#define L_SEQ 2048
#define DM    1024
#define NH    16
#define HD    64
#define BH    32
#define NEMB  1025
#define QRP   1056          // padded row pitch for g_qrel
#define MROWS 4096

#define MODE_PLAIN  0
#define MODE_HSPLIT 1
#define MODE_QREL   2

// ---------------- device scratch ----------------
__device__ __align__(16) float g_Q[BH * L_SEQ * HD];
__device__ __align__(16) float g_K[BH * L_SEQ * HD];
__device__ __align__(16) float g_V[BH * L_SEQ * HD];
__device__ __align__(16) float g_attn[MROWS * DM];
__device__ __align__(16) float g_qrel[BH * L_SEQ * QRP];
__device__ __align__(16) __nv_bfloat16 g_Ah[MROWS * DM];
__device__ __align__(16) __nv_bfloat16 g_Al[MROWS * DM];
__device__ __align__(16) __nv_bfloat16 g_Bh[DM * DM];
__device__ __align__(16) __nv_bfloat16 g_Bl[DM * DM];

// ---------------- helpers ----------------
static __device__ __forceinline__ uint32_t smem_u32(const void* p) {
    uint32_t a;
    asm("{ .reg .u64 t; cvta.to.shared.u64 t, %1; cvt.u32.u64 %0, t; }" : "=r"(a) : "l"(p));
    return a;
}
static __device__ __forceinline__ uint32_t swz(uint32_t b) { return b ^ ((b >> 3) & 0x70); }

static __device__ __forceinline__ void ldmx4(uint32_t* r, uint32_t addr) {
    asm volatile("ldmatrix.sync.aligned.m8n8.x4.shared.b16 {%0,%1,%2,%3}, [%4];"
                 : "=r"(r[0]), "=r"(r[1]), "=r"(r[2]), "=r"(r[3]) : "r"(addr));
}
static __device__ __forceinline__ void mma16816(float* c, const uint32_t* a, const uint32_t* b) {
    asm volatile("mma.sync.aligned.m16n8k16.row.col.f32.bf16.bf16.f32 "
                 "{%0,%1,%2,%3}, {%4,%5,%6,%7}, {%8,%9}, {%0,%1,%2,%3};"
                 : "+f"(c[0]), "+f"(c[1]), "+f"(c[2]), "+f"(c[3])
                 : "r"(a[0]), "r"(a[1]), "r"(a[2]), "r"(a[3]), "r"(b[0]), "r"(b[1]));
}
static __device__ __forceinline__ void cpasync16(uint32_t dst, const void* src, uint32_t ssz) {
    asm volatile("cp.async.cg.shared.global [%0], [%1], 16, %2;"
                 :: "r"(dst), "l"(src), "r"(ssz) : "memory");
}
static __device__ __forceinline__ void cp_commit() {
    asm volatile("cp.async.commit_group;" ::: "memory");
}

// ---------------- elementwise fp32 -> bf16 hi/lo split ----------------
__global__ void convert_split(const float* __restrict__ x,
                              __nv_bfloat16* __restrict__ hi,
                              __nv_bfloat16* __restrict__ lo, int n)
{
    int i = (blockIdx.x * blockDim.x + threadIdx.x) * 4;
    if (i >= n) return;
    float4 v = *(const float4*)(x + i);
    __nv_bfloat16 h0 = __float2bfloat16(v.x);
    __nv_bfloat16 h1 = __float2bfloat16(v.y);
    __nv_bfloat16 h2 = __float2bfloat16(v.z);
    __nv_bfloat16 h3 = __float2bfloat16(v.w);
    __nv_bfloat16 l0 = __float2bfloat16(v.x - __bfloat162float(h0));
    __nv_bfloat16 l1 = __float2bfloat16(v.y - __bfloat162float(h1));
    __nv_bfloat16 l2 = __float2bfloat16(v.z - __bfloat162float(h2));
    __nv_bfloat16 l3 = __float2bfloat16(v.w - __bfloat162float(h3));
    __nv_bfloat162* H = (__nv_bfloat162*)(hi + i);
    __nv_bfloat162* L = (__nv_bfloat162*)(lo + i);
    H[0] = __halves2bfloat162(h0, h1);
    H[1] = __halves2bfloat162(h2, h3);
    L[0] = __halves2bfloat162(l0, l1);
    L[1] = __halves2bfloat162(l2, l3);
}

// ---------------- W (KxN) -> W^T (NxK) with hi/lo split ----------------
__global__ void transpose_split(const float* __restrict__ W,
                                __nv_bfloat16* __restrict__ Th,
                                __nv_bfloat16* __restrict__ Tl)
{
    __shared__ float t[32][33];
    const int tx = threadIdx.x, ty = threadIdx.y;
    const int n = blockIdx.x * 32 + tx;
    const int k = blockIdx.y * 32 + ty;
    t[ty][tx] = W[k * DM + n];
    __syncthreads();
    const int on = blockIdx.x * 32 + ty;
    const int ok = blockIdx.y * 32 + tx;
    const float v = t[tx][ty];
    __nv_bfloat16 h = __float2bfloat16(v);
    Th[on * DM + ok] = h;
    Tl[on * DM + ok] = __float2bfloat16(v - __bfloat162float(h));
}

// =====================================================================
// HMMA GEMM: C(MxN) = A(MxK) @ B(NxK)^T + bias, split-bf16 (3 passes).
// 128x128 CTA tile, BK=64, 256 threads (8 warps, 4x2), double-buffered
// cp.async, SW128-xor swizzle + ldmatrix.
// =====================================================================
__global__ void __launch_bounds__(256) hmma_gemm(
    const __nv_bfloat16* __restrict__ Ah, const __nv_bfloat16* __restrict__ Al,
    const __nv_bfloat16* __restrict__ Bh, const __nv_bfloat16* __restrict__ Bl,
    const float* __restrict__ bias, float* __restrict__ C,
    int M, int N, int K, int mode)
{
    extern __shared__ char smc[];
    const uint32_t sb0 = smem_u32(smc);
    const uint32_t sbuf = (sb0 + 1023u) & ~1023u;    // 1024B aligned

    const int tid = threadIdx.x;
    const int wid = tid >> 5, lane = tid & 31;
    const int wm = wid & 3, wn = wid >> 2;
    const int bm = blockIdx.y << 7, bn = blockIdx.x << 7;

    float acc[2][8][4];
#pragma unroll
    for (int i = 0; i < 2; i++)
#pragma unroll
        for (int j = 0; j < 8; j++)
#pragma unroll
            for (int k = 0; k < 4; k++) acc[i][j][k] = 0.f;

    const int nc = K >> 6;

    auto issue_chunk = [&](int c) {
        const int k0 = c << 6;
        const uint32_t bufb = sbuf + (uint32_t)(c & 1) * 65536u;
#pragma unroll
        for (int t = 0; t < 4; t++) {
            const int u = tid + (t << 8);
            const int row = u >> 3, i = u & 7;
            const uint32_t so = swz((uint32_t)(row * 128 + i * 16));
            const size_t aoff = (((size_t)(bm + row) * K + k0) >> 3) + i;
            cpasync16(bufb + so,          (const uint4*)Ah + aoff, 16u);
            cpasync16(bufb + 16384u + so, (const uint4*)Al + aoff, 16u);
            const int nr = bn + row;
            const size_t boff = (((size_t)nr * K + k0) >> 3) + i;
            const uint32_t bsz = (nr < N) ? 16u : 0u;
            cpasync16(bufb + 32768u + so, (const uint4*)Bh + boff, bsz);
            cpasync16(bufb + 49152u + so, (const uint4*)Bl + boff, bsz);
        }
        cp_commit();
    };

    issue_chunk(0);
    if (nc > 1) issue_chunk(1);

    for (int c = 0; c < nc; c++) {
        if (c + 1 < nc) {
            asm volatile("cp.async.wait_group 1;" ::: "memory");
        } else {
            asm volatile("cp.async.wait_group 0;" ::: "memory");
        }
        __syncthreads();

        const uint32_t bufb = sbuf + (uint32_t)(c & 1) * 65536u;
#pragma unroll
        for (int kk = 0; kk < 4; kk++) {
            const uint32_t kb = (uint32_t)(kk << 5);
            uint32_t ah[8], al[8];
#pragma unroll
            for (int mf = 0; mf < 2; mf++) {
                const uint32_t r = (uint32_t)(wm * 32 + mf * 16 + (lane & 15));
                const uint32_t cb = kb + (uint32_t)((lane >> 4) << 4);
                const uint32_t adr = swz(r * 128 + cb);
                ldmx4(ah + mf * 4, bufb + adr);
                ldmx4(al + mf * 4, bufb + 16384u + adr);
            }
            uint32_t bh[16], bl[16];
#pragma unroll
            for (int nf2 = 0; nf2 < 4; nf2++) {
                const uint32_t r = (uint32_t)(wn * 64 + nf2 * 16 + (lane & 7) + ((lane >> 4) << 3));
                const uint32_t cb = kb + (uint32_t)(((lane >> 3) & 1) << 4);
                const uint32_t adr = swz(r * 128 + cb);
                ldmx4(bh + nf2 * 4, bufb + 32768u + adr);
                ldmx4(bl + nf2 * 4, bufb + 49152u + adr);
            }
#pragma unroll
            for (int mf = 0; mf < 2; mf++)
#pragma unroll
                for (int nf = 0; nf < 8; nf++) {
                    const int bi = (nf >> 1) * 4 + (nf & 1) * 2;
                    mma16816(acc[mf][nf], ah + mf * 4, bh + bi);
                    mma16816(acc[mf][nf], ah + mf * 4, bl + bi);
                    mma16816(acc[mf][nf], al + mf * 4, bh + bi);
                }
        }
        __syncthreads();
        if (c + 2 < nc) issue_chunk(c + 2);
    }

    // ---------------- epilogue ----------------
    const int gid = lane >> 2, tig = lane & 3;
#pragma unroll
    for (int mf = 0; mf < 2; mf++) {
        const int m0 = bm + wm * 32 + mf * 16 + gid;
#pragma unroll
        for (int nf = 0; nf < 8; nf++) {
            const int col = bn + wn * 64 + nf * 8 + tig * 2;
            float b0 = 0.f, b1 = 0.f;
            if (bias) { b0 = __ldg(bias + col); b1 = __ldg(bias + col + 1); }
            const float v00 = acc[mf][nf][0] + b0, v01 = acc[mf][nf][1] + b1;
            const float v10 = acc[mf][nf][2] + b0, v11 = acc[mf][nf][3] + b1;
            if (mode == MODE_HSPLIT) {
                const int h = col >> 6, d = col & 63;
                const int b_ = m0 >> 11, l0 = m0 & 2047;
                float* d0 = C + ((((size_t)b_ * NH + h) * L_SEQ + l0) * HD + d);
                float* d1 = C + ((((size_t)b_ * NH + h) * L_SEQ + l0 + 8) * HD + d);
                *(float2*)d0 = make_float2(v00, v01);
                *(float2*)d1 = make_float2(v10, v11);
            } else if (mode == MODE_PLAIN) {
                *(float2*)(C + (size_t)m0 * N + col) = make_float2(v00, v01);
                *(float2*)(C + (size_t)(m0 + 8) * N + col) = make_float2(v10, v11);
            } else { // MODE_QREL
                if (col + 1 < N) {
                    *(float2*)(C + (size_t)m0 * QRP + col) = make_float2(v00, v01);
                    *(float2*)(C + (size_t)(m0 + 8) * QRP + col) = make_float2(v10, v11);
                } else if (col < N) {
                    C[(size_t)m0 * QRP + col] = v00;
                    C[(size_t)(m0 + 8) * QRP + col] = v10;
                }
            }
        }
    }
}

// =====================================================================
// Flash attention (SIMT, fp32).
// =====================================================================
__global__ void __launch_bounds__(256) flash_kernel()
{
    extern __shared__ float sm[];
    float* sQ = sm;
    float* sK = sm + 64 * 65;
    float* sV = sm + 2 * 64 * 65;

    const int tid = threadIdx.x;
    const int tx = tid & 15, ty = tid >> 4;
    const int tx4 = tx << 2, ty4 = ty << 2;
    const int bh = blockIdx.y;
    const int i0 = blockIdx.x << 6;

    const float* Qb = g_Q + (size_t)bh * L_SEQ * HD;
    const float* Kb = g_K + (size_t)bh * L_SEQ * HD;
    const float* Vb = g_V + (size_t)bh * L_SEQ * HD;

    for (int idx = tid; idx < 1024; idx += 256) {
        const int r = idx >> 4;
        const int c = (idx & 15) << 2;
        float4 q4 = *(const float4*)(Qb + (size_t)(i0 + r) * 64 + c);
        sQ[r * 65 + c] = q4.x; sQ[r * 65 + c + 1] = q4.y;
        sQ[r * 65 + c + 2] = q4.z; sQ[r * 65 + c + 3] = q4.w;
    }

    float m_s[4], l_s[4], o[4][4];
#pragma unroll
    for (int i = 0; i < 4; i++) {
        m_s[i] = -1e30f; l_s[i] = 0.f;
#pragma unroll
        for (int j = 0; j < 4; j++) o[i][j] = 0.f;
    }

    const float SCL = 0.125f * 1.4426950408889634f;
    const float* qr[4];
#pragma unroll
    for (int i = 0; i < 4; i++)
        qr[i] = g_qrel + (size_t)(bh * L_SEQ + i0 + ty4 + i) * QRP + 512;

    for (int j0 = 0; j0 < L_SEQ; j0 += 64) {
        __syncthreads();
        for (int idx = tid; idx < 1024; idx += 256) {
            const int r = idx >> 4;
            const int c = (idx & 15) << 2;
            float4 k4 = *(const float4*)(Kb + (size_t)(j0 + r) * 64 + c);
            sK[r * 65 + c] = k4.x; sK[r * 65 + c + 1] = k4.y;
            sK[r * 65 + c + 2] = k4.z; sK[r * 65 + c + 3] = k4.w;
            *(float4*)(sV + r * 64 + c) = *(const float4*)(Vb + (size_t)(j0 + r) * 64 + c);
        }
        __syncthreads();

        float s[4][4];
#pragma unroll
        for (int i = 0; i < 4; i++)
#pragma unroll
            for (int j = 0; j < 4; j++) s[i][j] = 0.f;
#pragma unroll 8
        for (int k = 0; k < 64; k++) {
            float a[4], b[4];
#pragma unroll
            for (int i = 0; i < 4; i++) a[i] = sQ[(ty4 + i) * 65 + k];
#pragma unroll
            for (int j = 0; j < 4; j++) b[j] = sK[(tx4 + j) * 65 + k];
#pragma unroll
            for (int i = 0; i < 4; i++)
#pragma unroll
                for (int j = 0; j < 4; j++)
                    s[i][j] = fmaf(a[i], b[j], s[i][j]);
        }

#pragma unroll
        for (int i = 0; i < 4; i++) {
            const int ig = i0 + ty4 + i;
#pragma unroll
            for (int j = 0; j < 4; j++) {
                int rel = j0 + tx4 + j - ig;
                rel = max(-512, min(512, rel));
                s[i][j] = (s[i][j] + qr[i][rel]) * SCL;
            }
        }

#pragma unroll
        for (int i = 0; i < 4; i++) {
            float mt = fmaxf(fmaxf(s[i][0], s[i][1]), fmaxf(s[i][2], s[i][3]));
            mt = fmaxf(mt, __shfl_xor_sync(0xffffffffu, mt, 8));
            mt = fmaxf(mt, __shfl_xor_sync(0xffffffffu, mt, 4));
            mt = fmaxf(mt, __shfl_xor_sync(0xffffffffu, mt, 2));
            mt = fmaxf(mt, __shfl_xor_sync(0xffffffffu, mt, 1));
            const float mnew = fmaxf(m_s[i], mt);
            const float corr = exp2f(m_s[i] - mnew);
            m_s[i] = mnew;
            float rs = 0.f;
#pragma unroll
            for (int j = 0; j < 4; j++) {
                const float p = exp2f(s[i][j] - mnew);
                s[i][j] = p;
                rs += p;
            }
            rs += __shfl_xor_sync(0xffffffffu, rs, 8);
            rs += __shfl_xor_sync(0xffffffffu, rs, 4);
            rs += __shfl_xor_sync(0xffffffffu, rs, 2);
            rs += __shfl_xor_sync(0xffffffffu, rs, 1);
            l_s[i] = l_s[i] * corr + rs;
#pragma unroll
            for (int j = 0; j < 4; j++) o[i][j] *= corr;
        }

        __syncthreads();
#pragma unroll
        for (int i = 0; i < 4; i++)
#pragma unroll
            for (int j = 0; j < 4; j++)
                sK[(ty4 + i) * 65 + tx4 + j] = s[i][j];
        __syncthreads();

#pragma unroll 8
        for (int k = 0; k < 64; k++) {
            float p[4];
#pragma unroll
            for (int i = 0; i < 4; i++) p[i] = sK[(ty4 + i) * 65 + k];
            const float4 v4 = *(const float4*)(sV + k * 64 + tx4);
#pragma unroll
            for (int i = 0; i < 4; i++) {
                o[i][0] = fmaf(p[i], v4.x, o[i][0]);
                o[i][1] = fmaf(p[i], v4.y, o[i][1]);
                o[i][2] = fmaf(p[i], v4.z, o[i][2]);
                o[i][3] = fmaf(p[i], v4.w, o[i][3]);
            }
        }
    }

    const int bb = bh >> 4;
    const int h = bh & 15;
#pragma unroll
    for (int i = 0; i < 4; i++) {
        const float inv = 1.f / l_s[i];
        const size_t row = (size_t)(bb * L_SEQ + i0 + ty4 + i);
        float4 val = make_float4(o[i][0] * inv, o[i][1] * inv, o[i][2] * inv, o[i][3] * inv);
        *(float4*)(g_attn + row * DM + h * 64 + tx4) = val;
    }
}

// =====================================================================
extern "C" void kernel_launch(void* const* d_in, const int* in_sizes, int n_in,
                              void* d_out, int out_size)
{
    const float* query = (const float*)d_in[0];
    const float* key   = (const float*)d_in[1];
    const float* value = (const float*)d_in[2];
    const float* wq    = (const float*)d_in[3];
    const float* bq    = (const float*)d_in[4];
    const float* wk    = (const float*)d_in[5];
    const float* bk    = (const float*)d_in[6];
    const float* wv    = (const float*)d_in[7];
    const float* bv    = (const float*)d_in[8];
    const float* wo    = (const float*)d_in[9];
    const float* bo    = (const float*)d_in[10];
    const float* rel   = (const float*)d_in[11];

    float *pQ, *pK, *pV, *pAttn, *pQrel;
    __nv_bfloat16 *pAh, *pAl, *pBh, *pBl;
    cudaGetSymbolAddress((void**)&pQ, g_Q);
    cudaGetSymbolAddress((void**)&pK, g_K);
    cudaGetSymbolAddress((void**)&pV, g_V);
    cudaGetSymbolAddress((void**)&pAttn, g_attn);
    cudaGetSymbolAddress((void**)&pQrel, g_qrel);
    cudaGetSymbolAddress((void**)&pAh, g_Ah);
    cudaGetSymbolAddress((void**)&pAl, g_Al);
    cudaGetSymbolAddress((void**)&pBh, g_Bh);
    cudaGetSymbolAddress((void**)&pBl, g_Bl);

    const int GEMM_SMEM = 2 * 65536 + 1024;   // 132096
    cudaFuncSetAttribute(hmma_gemm, cudaFuncAttributeMaxDynamicSharedMemorySize, GEMM_SMEM);
    const int FLASH_SMEM = (64 * 65 * 2 + 64 * 64) * (int)sizeof(float);
    cudaFuncSetAttribute(flash_kernel, cudaFuncAttributeMaxDynamicSharedMemorySize, FLASH_SMEM);

    const dim3 tpose_grid(32, 32), tpose_blk(32, 32);
    const dim3 proj_grid(8, 32);
    const int  NELEM = MROWS * DM;

    // ---- Q projection ----
    transpose_split<<<tpose_grid, tpose_blk>>>(wq, pBh, pBl);
    convert_split<<<4096, 256>>>(query, pAh, pAl, NELEM);
    hmma_gemm<<<proj_grid, 256, GEMM_SMEM>>>(pAh, pAl, pBh, pBl, bq, pQ, MROWS, DM, DM, MODE_HSPLIT);
    // ---- K projection ----
    transpose_split<<<tpose_grid, tpose_blk>>>(wk, pBh, pBl);
    convert_split<<<4096, 256>>>(key, pAh, pAl, NELEM);
    hmma_gemm<<<proj_grid, 256, GEMM_SMEM>>>(pAh, pAl, pBh, pBl, bk, pK, MROWS, DM, DM, MODE_HSPLIT);
    // ---- V projection ----
    transpose_split<<<tpose_grid, tpose_blk>>>(wv, pBh, pBl);
    convert_split<<<4096, 256>>>(value, pAh, pAl, NELEM);
    hmma_gemm<<<proj_grid, 256, GEMM_SMEM>>>(pAh, pAl, pBh, pBl, bv, pV, MROWS, DM, DM, MODE_HSPLIT);

    // ---- q_rel = Qh @ rel_emb^T : M=65536, N=1025, K=64 ----
    convert_split<<<4096, 256>>>(pQ, pAh, pAl, NELEM);
    convert_split<<<65, 256>>>(rel, pBh, pBl, NEMB * HD);
    hmma_gemm<<<dim3(9, 512), 256, GEMM_SMEM>>>(pAh, pAl, pBh, pBl, nullptr, pQrel,
                                                BH * L_SEQ, NEMB, HD, MODE_QREL);

    // ---- attention ----
    flash_kernel<<<dim3(32, 32), 256, FLASH_SMEM>>>();

    // ---- output projection ----
    convert_split<<<4096, 256>>>(pAttn, pAh, pAl, NELEM);
    transpose_split<<<tpose_grid, tpose_blk>>>(wo, pBh, pBl);
    hmma_gemm<<<proj_grid, 256, GEMM_SMEM>>>(pAh, pAl, pBh, pBl, bo, (float*)d_out, MROWS, DM, DM, MODE_PLAIN);
}

// round 4
// speedup vs baseline: 2.4863x; 1.5493x over previous
#include <cuda_runtime.h>
#include <cuda_bf16.h>
#include <stdint.h>
#include <math.h>

// Problem constants
#define L_SEQ 2048
#define DM    1024
#define NH    16
#define HD    64
#define BH    32
#define NEMB  1025
#define QRP   1056
#define MROWS 4096

#define MODE_PLAIN  0
#define MODE_HSPLIT 1
#define MODE_QREL   2

// ---------------- device scratch ----------------
__device__ __align__(16) float g_qrel[BH * L_SEQ * QRP];
__device__ __align__(16) __nv_bfloat16 g_Qh[BH * L_SEQ * HD];
__device__ __align__(16) __nv_bfloat16 g_Ql[BH * L_SEQ * HD];
__device__ __align__(16) __nv_bfloat16 g_Kh[BH * L_SEQ * HD];
__device__ __align__(16) __nv_bfloat16 g_Kl[BH * L_SEQ * HD];
__device__ __align__(16) __nv_bfloat16 g_Vh[BH * L_SEQ * HD];
__device__ __align__(16) __nv_bfloat16 g_Vl[BH * L_SEQ * HD];
__device__ __align__(16) __nv_bfloat16 g_Ah[MROWS * DM];
__device__ __align__(16) __nv_bfloat16 g_Al[MROWS * DM];
__device__ __align__(16) __nv_bfloat16 g_Bh[DM * DM];
__device__ __align__(16) __nv_bfloat16 g_Bl[DM * DM];

// ---------------- helpers ----------------
static __device__ __forceinline__ uint32_t smem_u32(const void* p) {
    uint32_t a;
    asm("{ .reg .u64 t; cvta.to.shared.u64 t, %1; cvt.u32.u64 %0, t; }" : "=r"(a) : "l"(p));
    return a;
}
static __device__ __forceinline__ uint32_t swz(uint32_t b) { return b ^ ((b >> 3) & 0x70); }

static __device__ __forceinline__ void ldmx4(uint32_t* r, uint32_t addr) {
    asm volatile("ldmatrix.sync.aligned.m8n8.x4.shared.b16 {%0,%1,%2,%3}, [%4];"
                 : "=r"(r[0]), "=r"(r[1]), "=r"(r[2]), "=r"(r[3]) : "r"(addr));
}
static __device__ __forceinline__ void ldmx4t(uint32_t* r, uint32_t addr) {
    asm volatile("ldmatrix.sync.aligned.m8n8.x4.trans.shared.b16 {%0,%1,%2,%3}, [%4];"
                 : "=r"(r[0]), "=r"(r[1]), "=r"(r[2]), "=r"(r[3]) : "r"(addr));
}
static __device__ __forceinline__ void mma16816(float* c, const uint32_t* a, const uint32_t* b) {
    asm volatile("mma.sync.aligned.m16n8k16.row.col.f32.bf16.bf16.f32 "
                 "{%0,%1,%2,%3}, {%4,%5,%6,%7}, {%8,%9}, {%0,%1,%2,%3};"
                 : "+f"(c[0]), "+f"(c[1]), "+f"(c[2]), "+f"(c[3])
                 : "r"(a[0]), "r"(a[1]), "r"(a[2]), "r"(a[3]), "r"(b[0]), "r"(b[1]));
}
static __device__ __forceinline__ void cpasync16(uint32_t dst, const void* src, uint32_t ssz) {
    asm volatile("cp.async.cg.shared.global [%0], [%1], 16, %2;"
                 :: "r"(dst), "l"(src), "r"(ssz) : "memory");
}
static __device__ __forceinline__ void cp_commit() {
    asm volatile("cp.async.commit_group;" ::: "memory");
}

// ---------------- elementwise fp32 -> bf16 hi/lo split ----------------
__global__ void convert_split(const float* __restrict__ x,
                              __nv_bfloat16* __restrict__ hi,
                              __nv_bfloat16* __restrict__ lo, int n)
{
    int i = (blockIdx.x * blockDim.x + threadIdx.x) * 4;
    if (i >= n) return;
    float4 v = *(const float4*)(x + i);
    __nv_bfloat16 h0 = __float2bfloat16(v.x);
    __nv_bfloat16 h1 = __float2bfloat16(v.y);
    __nv_bfloat16 h2 = __float2bfloat16(v.z);
    __nv_bfloat16 h3 = __float2bfloat16(v.w);
    __nv_bfloat16 l0 = __float2bfloat16(v.x - __bfloat162float(h0));
    __nv_bfloat16 l1 = __float2bfloat16(v.y - __bfloat162float(h1));
    __nv_bfloat16 l2 = __float2bfloat16(v.z - __bfloat162float(h2));
    __nv_bfloat16 l3 = __float2bfloat16(v.w - __bfloat162float(h3));
    __nv_bfloat162* H = (__nv_bfloat162*)(hi + i);
    __nv_bfloat162* L = (__nv_bfloat162*)(lo + i);
    H[0] = __halves2bfloat162(h0, h1);
    H[1] = __halves2bfloat162(h2, h3);
    L[0] = __halves2bfloat162(l0, l1);
    L[1] = __halves2bfloat162(l2, l3);
}

// ---------------- W (KxN) -> W^T (NxK) with hi/lo split ----------------
__global__ void transpose_split(const float* __restrict__ W,
                                __nv_bfloat16* __restrict__ Th,
                                __nv_bfloat16* __restrict__ Tl)
{
    __shared__ float t[32][33];
    const int tx = threadIdx.x, ty = threadIdx.y;
    const int n = blockIdx.x * 32 + tx;
    const int k = blockIdx.y * 32 + ty;
    t[ty][tx] = W[k * DM + n];
    __syncthreads();
    const int on = blockIdx.x * 32 + ty;
    const int ok = blockIdx.y * 32 + tx;
    const float v = t[tx][ty];
    __nv_bfloat16 h = __float2bfloat16(v);
    Th[on * DM + ok] = h;
    Tl[on * DM + ok] = __float2bfloat16(v - __bfloat162float(h));
}

// =====================================================================
// HMMA GEMM: C(MxN) = A(MxK) @ B(NxK)^T + bias, split-bf16 (3 passes).
// Epilogue modes: PLAIN -> fp32 C; HSPLIT -> head-split bf16 hi/lo pair;
// QREL -> fp32 with QRP pitch.
// =====================================================================
__global__ void __launch_bounds__(256) hmma_gemm(
    const __nv_bfloat16* __restrict__ Ah, const __nv_bfloat16* __restrict__ Al,
    const __nv_bfloat16* __restrict__ Bh, const __nv_bfloat16* __restrict__ Bl,
    const float* __restrict__ bias, float* __restrict__ C,
    __nv_bfloat16* __restrict__ Ch, __nv_bfloat16* __restrict__ Cl,
    int M, int N, int K, int mode)
{
    extern __shared__ char smc[];
    const uint32_t sb0 = smem_u32(smc);
    const uint32_t sbuf = (sb0 + 1023u) & ~1023u;

    const int tid = threadIdx.x;
    const int wid = tid >> 5, lane = tid & 31;
    const int wm = wid & 3, wn = wid >> 2;
    const int bm = blockIdx.y << 7, bn = blockIdx.x << 7;

    float acc[2][8][4];
#pragma unroll
    for (int i = 0; i < 2; i++)
#pragma unroll
        for (int j = 0; j < 8; j++)
#pragma unroll
            for (int k = 0; k < 4; k++) acc[i][j][k] = 0.f;

    const int nc = K >> 6;

    auto issue_chunk = [&](int c) {
        const int k0 = c << 6;
        const uint32_t bufb = sbuf + (uint32_t)(c & 1) * 65536u;
#pragma unroll
        for (int t = 0; t < 4; t++) {
            const int u = tid + (t << 8);
            const int row = u >> 3, i = u & 7;
            const uint32_t so = swz((uint32_t)(row * 128 + i * 16));
            const size_t aoff = (((size_t)(bm + row) * K + k0) >> 3) + i;
            cpasync16(bufb + so,          (const uint4*)Ah + aoff, 16u);
            cpasync16(bufb + 16384u + so, (const uint4*)Al + aoff, 16u);
            const int nr = bn + row;
            const size_t boff = (((size_t)nr * K + k0) >> 3) + i;
            const uint32_t bsz = (nr < N) ? 16u : 0u;
            cpasync16(bufb + 32768u + so, (const uint4*)Bh + boff, bsz);
            cpasync16(bufb + 49152u + so, (const uint4*)Bl + boff, bsz);
        }
        cp_commit();
    };

    issue_chunk(0);
    if (nc > 1) issue_chunk(1);

    for (int c = 0; c < nc; c++) {
        if (c + 1 < nc) {
            asm volatile("cp.async.wait_group 1;" ::: "memory");
        } else {
            asm volatile("cp.async.wait_group 0;" ::: "memory");
        }
        __syncthreads();

        const uint32_t bufb = sbuf + (uint32_t)(c & 1) * 65536u;
#pragma unroll
        for (int kk = 0; kk < 4; kk++) {
            const uint32_t kb = (uint32_t)(kk << 5);
            uint32_t ah[8], al[8];
#pragma unroll
            for (int mf = 0; mf < 2; mf++) {
                const uint32_t r = (uint32_t)(wm * 32 + mf * 16 + (lane & 15));
                const uint32_t cb = kb + (uint32_t)((lane >> 4) << 4);
                const uint32_t adr = swz(r * 128 + cb);
                ldmx4(ah + mf * 4, bufb + adr);
                ldmx4(al + mf * 4, bufb + 16384u + adr);
            }
            uint32_t bh[16], bl[16];
#pragma unroll
            for (int nf2 = 0; nf2 < 4; nf2++) {
                const uint32_t r = (uint32_t)(wn * 64 + nf2 * 16 + (lane & 7) + ((lane >> 4) << 3));
                const uint32_t cb = kb + (uint32_t)(((lane >> 3) & 1) << 4);
                const uint32_t adr = swz(r * 128 + cb);
                ldmx4(bh + nf2 * 4, bufb + 32768u + adr);
                ldmx4(bl + nf2 * 4, bufb + 49152u + adr);
            }
#pragma unroll
            for (int mf = 0; mf < 2; mf++)
#pragma unroll
                for (int nf = 0; nf < 8; nf++) {
                    const int bi = (nf >> 1) * 4 + (nf & 1) * 2;
                    mma16816(acc[mf][nf], ah + mf * 4, bh + bi);
                    mma16816(acc[mf][nf], ah + mf * 4, bl + bi);
                    mma16816(acc[mf][nf], al + mf * 4, bh + bi);
                }
        }
        __syncthreads();
        if (c + 2 < nc) issue_chunk(c + 2);
    }

    // ---------------- epilogue ----------------
    const int gid = lane >> 2, tig = lane & 3;
#pragma unroll
    for (int mf = 0; mf < 2; mf++) {
        const int m0 = bm + wm * 32 + mf * 16 + gid;
#pragma unroll
        for (int nf = 0; nf < 8; nf++) {
            const int col = bn + wn * 64 + nf * 8 + tig * 2;
            float b0 = 0.f, b1 = 0.f;
            if (bias) { b0 = __ldg(bias + col); b1 = __ldg(bias + col + 1); }
            const float v00 = acc[mf][nf][0] + b0, v01 = acc[mf][nf][1] + b1;
            const float v10 = acc[mf][nf][2] + b0, v11 = acc[mf][nf][3] + b1;
            if (mode == MODE_HSPLIT) {
                const int h = col >> 6, d = col & 63;
                const int b_ = m0 >> 11, l0 = m0 & 2047;
                const size_t o0 = (((size_t)b_ * NH + h) * L_SEQ + l0) * HD + d;
                const size_t o1 = o0 + (size_t)8 * HD;
                __nv_bfloat16 h00 = __float2bfloat16(v00), h01 = __float2bfloat16(v01);
                __nv_bfloat16 h10 = __float2bfloat16(v10), h11 = __float2bfloat16(v11);
                *(__nv_bfloat162*)(Ch + o0) = __halves2bfloat162(h00, h01);
                *(__nv_bfloat162*)(Ch + o1) = __halves2bfloat162(h10, h11);
                *(__nv_bfloat162*)(Cl + o0) = __halves2bfloat162(
                    __float2bfloat16(v00 - __bfloat162float(h00)),
                    __float2bfloat16(v01 - __bfloat162float(h01)));
                *(__nv_bfloat162*)(Cl + o1) = __halves2bfloat162(
                    __float2bfloat16(v10 - __bfloat162float(h10)),
                    __float2bfloat16(v11 - __bfloat162float(h11)));
            } else if (mode == MODE_PLAIN) {
                *(float2*)(C + (size_t)m0 * N + col) = make_float2(v00, v01);
                *(float2*)(C + (size_t)(m0 + 8) * N + col) = make_float2(v10, v11);
            } else { // MODE_QREL
                if (col + 1 < N) {
                    *(float2*)(C + (size_t)m0 * QRP + col) = make_float2(v00, v01);
                    *(float2*)(C + (size_t)(m0 + 8) * QRP + col) = make_float2(v10, v11);
                } else if (col < N) {
                    C[(size_t)m0 * QRP + col] = v00;
                    C[(size_t)(m0 + 8) * QRP + col] = v10;
                }
            }
        }
    }
}

// =====================================================================
// Flash attention, HMMA split-bf16.
// Grid (L/128, BH), 256 threads = 8 warps x 16 rows.
// =====================================================================
#define FLASH_SMEM_BYTES 167936
__global__ void __launch_bounds__(256) flash_hmma()
{
    extern __shared__ char smc[];
    const uint32_t sb = smem_u32(smc);
    char* pQh = smc;            char* pQl = smc + 16384;
    char* pKh = smc + 32768;    char* pKl = smc + 49152;
    char* pVh = smc + 65536;    char* pVl = smc + 81920;
    char* pPh = smc + 98304;    char* pPl = smc + 133120;
    const uint32_t uQh = sb,          uQl = sb + 16384;
    const uint32_t uKh = sb + 32768,  uKl = sb + 49152;
    const uint32_t uVh = sb + 65536,  uVl = sb + 81920;
    const uint32_t uPh = sb + 98304,  uPl = sb + 133120;

    const int tid = threadIdx.x, w = tid >> 5, lane = tid & 31;
    const int tig = lane & 3, grp = lane >> 2;
    const int bh = blockIdx.y, i0 = blockIdx.x << 7;

    // load Q tile (hi/lo)
    const uint4* gQh = (const uint4*)(g_Qh + (size_t)(bh * L_SEQ + i0) * HD);
    const uint4* gQl = (const uint4*)(g_Ql + (size_t)(bh * L_SEQ + i0) * HD);
#pragma unroll
    for (int t = 0; t < 4; t++) {
        const int u = tid + (t << 8);
        const int r = u >> 3, i = u & 7;
        const uint32_t so = swz((uint32_t)(r * 128 + i * 16));
        *(uint4*)(pQh + so) = gQh[r * 8 + i];
        *(uint4*)(pQl + so) = gQl[r * 8 + i];
    }

    float O[8][4];
#pragma unroll
    for (int i = 0; i < 8; i++)
#pragma unroll
        for (int j = 0; j < 4; j++) O[i][j] = 0.f;
    float m_a = -1e30f, m_b = -1e30f, l_a = 0.f, l_b = 0.f;

    const int ia = i0 + w * 16 + grp, ib = ia + 8;
    const float* qra = g_qrel + (size_t)(bh * L_SEQ + ia) * QRP + 512;
    const float* qrb = g_qrel + (size_t)(bh * L_SEQ + ib) * QRP + 512;

    const uint4* gKh = (const uint4*)(g_Kh + (size_t)bh * L_SEQ * HD);
    const uint4* gKl = (const uint4*)(g_Kl + (size_t)bh * L_SEQ * HD);
    const uint4* gVh = (const uint4*)(g_Vh + (size_t)bh * L_SEQ * HD);
    const uint4* gVl = (const uint4*)(g_Vl + (size_t)bh * L_SEQ * HD);

    const float SCL = 0.125f * 1.4426950408889634f;

    for (int j0 = 0; j0 < L_SEQ; j0 += 128) {
        __syncthreads();
#pragma unroll
        for (int t = 0; t < 4; t++) {
            const int u = tid + (t << 8);
            const int r = u >> 3, i = u & 7;
            const uint32_t so = swz((uint32_t)(r * 128 + i * 16));
            const size_t gi = (size_t)(j0 + r) * 8 + i;
            *(uint4*)(pKh + so) = gKh[gi];
            *(uint4*)(pKl + so) = gKl[gi];
            *(uint4*)(pVh + so) = gVh[gi];
            *(uint4*)(pVl + so) = gVl[gi];
        }
        __syncthreads();

        // ---- S = QK^T (split, 3 passes) ----
        float s[16][4];
#pragma unroll
        for (int i = 0; i < 16; i++)
#pragma unroll
            for (int j = 0; j < 4; j++) s[i][j] = 0.f;

        const uint32_t ra = (uint32_t)(w * 16 + (lane & 15));
#pragma unroll
        for (int kk = 0; kk < 4; kk++) {
            const uint32_t kb = (uint32_t)(kk << 5);
            const uint32_t aadr = swz(ra * 128 + kb + (uint32_t)((lane >> 4) << 4));
            uint32_t qh4[4], ql4[4];
            ldmx4(qh4, uQh + aadr);
            ldmx4(ql4, uQl + aadr);
#pragma unroll
            for (int g = 0; g < 8; g++) {
                const uint32_t rb = (uint32_t)(g * 16 + (lane & 7) + ((lane >> 4) << 3));
                const uint32_t badr = swz(rb * 128 + kb + (uint32_t)(((lane >> 3) & 1) << 4));
                uint32_t kh4[4], kl4[4];
                ldmx4(kh4, uKh + badr);
                ldmx4(kl4, uKl + badr);
                mma16816(s[2 * g],     qh4, kh4);
                mma16816(s[2 * g],     qh4, kl4);
                mma16816(s[2 * g],     ql4, kh4);
                mma16816(s[2 * g + 1], qh4, kh4 + 2);
                mma16816(s[2 * g + 1], qh4, kl4 + 2);
                mma16816(s[2 * g + 1], ql4, kh4 + 2);
            }
        }

        // ---- + positional term, scale to exp2 domain ----
#pragma unroll
        for (int nf = 0; nf < 16; nf++) {
            const int j = j0 + nf * 8 + tig * 2;
            const int e0a = min(max(j - ia, -512), 512);
            const int e1a = min(max(j + 1 - ia, -512), 512);
            const int e0b = min(max(j - ib, -512), 512);
            const int e1b = min(max(j + 1 - ib, -512), 512);
            s[nf][0] = (s[nf][0] + __ldg(qra + e0a)) * SCL;
            s[nf][1] = (s[nf][1] + __ldg(qra + e1a)) * SCL;
            s[nf][2] = (s[nf][2] + __ldg(qrb + e0b)) * SCL;
            s[nf][3] = (s[nf][3] + __ldg(qrb + e1b)) * SCL;
        }

        // ---- online softmax (rows fully inside quad) ----
        float ma = -1e30f, mb = -1e30f;
#pragma unroll
        for (int nf = 0; nf < 16; nf++) {
            ma = fmaxf(ma, fmaxf(s[nf][0], s[nf][1]));
            mb = fmaxf(mb, fmaxf(s[nf][2], s[nf][3]));
        }
        ma = fmaxf(ma, __shfl_xor_sync(0xffffffffu, ma, 1));
        ma = fmaxf(ma, __shfl_xor_sync(0xffffffffu, ma, 2));
        mb = fmaxf(mb, __shfl_xor_sync(0xffffffffu, mb, 1));
        mb = fmaxf(mb, __shfl_xor_sync(0xffffffffu, mb, 2));
        const float mna = fmaxf(m_a, ma), mnb = fmaxf(m_b, mb);
        const float ca = exp2f(m_a - mna), cb = exp2f(m_b - mnb);
        m_a = mna; m_b = mnb;

        __syncwarp();
        char* wPa = pPh + (w * 16 + grp) * 272;
        char* wPb = wPa + 8 * 272;
        char* wLa = pPl + (w * 16 + grp) * 272;
        char* wLb = wLa + 8 * 272;
        float sa = 0.f, sb2 = 0.f;
#pragma unroll
        for (int nf = 0; nf < 16; nf++) {
            const float p0 = exp2f(s[nf][0] - m_a);
            const float p1 = exp2f(s[nf][1] - m_a);
            const float p2 = exp2f(s[nf][2] - m_b);
            const float p3 = exp2f(s[nf][3] - m_b);
            sa += p0 + p1;
            sb2 += p2 + p3;
            const int cbyte = nf * 16 + tig * 4;
            __nv_bfloat16 h0 = __float2bfloat16(p0), h1 = __float2bfloat16(p1);
            __nv_bfloat16 h2 = __float2bfloat16(p2), h3 = __float2bfloat16(p3);
            *(__nv_bfloat162*)(wPa + cbyte) = __halves2bfloat162(h0, h1);
            *(__nv_bfloat162*)(wPb + cbyte) = __halves2bfloat162(h2, h3);
            *(__nv_bfloat162*)(wLa + cbyte) = __halves2bfloat162(
                __float2bfloat16(p0 - __bfloat162float(h0)),
                __float2bfloat16(p1 - __bfloat162float(h1)));
            *(__nv_bfloat162*)(wLb + cbyte) = __halves2bfloat162(
                __float2bfloat16(p2 - __bfloat162float(h2)),
                __float2bfloat16(p3 - __bfloat162float(h3)));
        }
        sa += __shfl_xor_sync(0xffffffffu, sa, 1);
        sa += __shfl_xor_sync(0xffffffffu, sa, 2);
        sb2 += __shfl_xor_sync(0xffffffffu, sb2, 1);
        sb2 += __shfl_xor_sync(0xffffffffu, sb2, 2);
        l_a = l_a * ca + sa;
        l_b = l_b * cb + sb2;
#pragma unroll
        for (int nf2 = 0; nf2 < 8; nf2++) {
            O[nf2][0] *= ca; O[nf2][1] *= ca;
            O[nf2][2] *= cb; O[nf2][3] *= cb;
        }
        __syncwarp();

        // ---- O += P V (split, 3 passes) ----
#pragma unroll
        for (int k = 0; k < 8; k++) {
            const uint32_t kb = (uint32_t)(k << 5);
            const uint32_t padr = (uint32_t)((w * 16 + (lane & 15)) * 272 + kb + ((lane >> 4) << 4));
            uint32_t ph4[4], pl4[4];
            ldmx4(ph4, uPh + padr);
            ldmx4(pl4, uPl + padr);
#pragma unroll
            for (int g = 0; g < 4; g++) {
                const uint32_t rv = (uint32_t)(k * 16 + (lane & 7) + (((lane >> 3) & 1) << 3));
                const uint32_t vadr = swz(rv * 128 + (uint32_t)(g * 32) + (uint32_t)((lane >> 4) << 4));
                uint32_t vh4[4], vl4[4];
                ldmx4t(vh4, uVh + vadr);
                ldmx4t(vl4, uVl + vadr);
                mma16816(O[2 * g],     ph4, vh4);
                mma16816(O[2 * g],     ph4, vl4);
                mma16816(O[2 * g],     pl4, vh4);
                mma16816(O[2 * g + 1], ph4, vh4 + 2);
                mma16816(O[2 * g + 1], ph4, vl4 + 2);
                mma16816(O[2 * g + 1], pl4, vh4 + 2);
            }
        }
    }

    // ---- epilogue: normalize, write bf16 hi/lo merged-head ----
    const float inva = 1.f / l_a, invb = 1.f / l_b;
    const int b_ = bh >> 4, h = bh & 15;
    const size_t rowa = (size_t)b_ * L_SEQ + (i0 + w * 16 + grp);
    const size_t rowb = rowa + 8;
#pragma unroll
    for (int nf2 = 0; nf2 < 8; nf2++) {
        const int col = h * 64 + nf2 * 8 + tig * 2;
        const float v0 = O[nf2][0] * inva, v1 = O[nf2][1] * inva;
        const float v2 = O[nf2][2] * invb, v3 = O[nf2][3] * invb;
        __nv_bfloat16 h0 = __float2bfloat16(v0), h1 = __float2bfloat16(v1);
        __nv_bfloat16 h2 = __float2bfloat16(v2), h3 = __float2bfloat16(v3);
        *(__nv_bfloat162*)(g_Ah + rowa * DM + col) = __halves2bfloat162(h0, h1);
        *(__nv_bfloat162*)(g_Ah + rowb * DM + col) = __halves2bfloat162(h2, h3);
        *(__nv_bfloat162*)(g_Al + rowa * DM + col) = __halves2bfloat162(
            __float2bfloat16(v0 - __bfloat162float(h0)),
            __float2bfloat16(v1 - __bfloat162float(h1)));
        *(__nv_bfloat162*)(g_Al + rowb * DM + col) = __halves2bfloat162(
            __float2bfloat16(v2 - __bfloat162float(h2)),
            __float2bfloat16(v3 - __bfloat162float(h3)));
    }
}

// =====================================================================
extern "C" void kernel_launch(void* const* d_in, const int* in_sizes, int n_in,
                              void* d_out, int out_size)
{
    const float* query = (const float*)d_in[0];
    const float* key   = (const float*)d_in[1];
    const float* value = (const float*)d_in[2];
    const float* wq    = (const float*)d_in[3];
    const float* bq    = (const float*)d_in[4];
    const float* wk    = (const float*)d_in[5];
    const float* bk    = (const float*)d_in[6];
    const float* wv    = (const float*)d_in[7];
    const float* bv    = (const float*)d_in[8];
    const float* wo    = (const float*)d_in[9];
    const float* bo    = (const float*)d_in[10];
    const float* rel   = (const float*)d_in[11];

    float* pQrel;
    __nv_bfloat16 *pQh, *pQl, *pKh, *pKl, *pVh, *pVl, *pAh, *pAl, *pBh, *pBl;
    cudaGetSymbolAddress((void**)&pQrel, g_qrel);
    cudaGetSymbolAddress((void**)&pQh, g_Qh);
    cudaGetSymbolAddress((void**)&pQl, g_Ql);
    cudaGetSymbolAddress((void**)&pKh, g_Kh);
    cudaGetSymbolAddress((void**)&pKl, g_Kl);
    cudaGetSymbolAddress((void**)&pVh, g_Vh);
    cudaGetSymbolAddress((void**)&pVl, g_Vl);
    cudaGetSymbolAddress((void**)&pAh, g_Ah);
    cudaGetSymbolAddress((void**)&pAl, g_Al);
    cudaGetSymbolAddress((void**)&pBh, g_Bh);
    cudaGetSymbolAddress((void**)&pBl, g_Bl);

    const int GEMM_SMEM = 2 * 65536 + 1024;
    cudaFuncSetAttribute(hmma_gemm, cudaFuncAttributeMaxDynamicSharedMemorySize, GEMM_SMEM);
    cudaFuncSetAttribute(flash_hmma, cudaFuncAttributeMaxDynamicSharedMemorySize, FLASH_SMEM_BYTES);

    const dim3 tpose_grid(32, 32), tpose_blk(32, 32);
    const dim3 proj_grid(8, 32);
    const int  NELEM = MROWS * DM;

    // ---- Q projection -> bf16 hi/lo head-split ----
    transpose_split<<<tpose_grid, tpose_blk>>>(wq, pBh, pBl);
    convert_split<<<4096, 256>>>(query, pAh, pAl, NELEM);
    hmma_gemm<<<proj_grid, 256, GEMM_SMEM>>>(pAh, pAl, pBh, pBl, bq, nullptr, pQh, pQl,
                                             MROWS, DM, DM, MODE_HSPLIT);
    // ---- K projection ----
    transpose_split<<<tpose_grid, tpose_blk>>>(wk, pBh, pBl);
    convert_split<<<4096, 256>>>(key, pAh, pAl, NELEM);
    hmma_gemm<<<proj_grid, 256, GEMM_SMEM>>>(pAh, pAl, pBh, pBl, bk, nullptr, pKh, pKl,
                                             MROWS, DM, DM, MODE_HSPLIT);
    // ---- V projection ----
    transpose_split<<<tpose_grid, tpose_blk>>>(wv, pBh, pBl);
    convert_split<<<4096, 256>>>(value, pAh, pAl, NELEM);
    hmma_gemm<<<proj_grid, 256, GEMM_SMEM>>>(pAh, pAl, pBh, pBl, bv, nullptr, pVh, pVl,
                                             MROWS, DM, DM, MODE_HSPLIT);

    // ---- q_rel = Qh @ rel_emb^T (M=65536, N=1025, K=64) ----
    convert_split<<<65, 256>>>(rel, pBh, pBl, NEMB * HD);
    hmma_gemm<<<dim3(9, 512), 256, GEMM_SMEM>>>(pQh, pQl, pBh, pBl, nullptr, pQrel,
                                                nullptr, nullptr,
                                                BH * L_SEQ, NEMB, HD, MODE_QREL);

    // ---- attention (HMMA flash) -> g_Ah/g_Al merged-head bf16 hi/lo ----
    flash_hmma<<<dim3(16, 32), 256, FLASH_SMEM_BYTES>>>();

    // ---- output projection ----
    transpose_split<<<tpose_grid, tpose_blk>>>(wo, pBh, pBl);
    hmma_gemm<<<proj_grid, 256, GEMM_SMEM>>>(pAh, pAl, pBh, pBl, bo, (float*)d_out,
                                             nullptr, nullptr, MROWS, DM, DM, MODE_PLAIN);
}

// round 5
// speedup vs baseline: 3.0021x; 1.2074x over previous
#include <cuda_runtime.h>
#include <cuda_bf16.h>
#include <cuda_fp16.h>
#include <stdint.h>
#include <math.h>

// Problem constants
#define L_SEQ 2048
#define DM    1024
#define NH    16
#define HD    64
#define BH    32
#define NEMB  1025
#define QRP   1056
#define MROWS 4096

#define MODE_PLAIN 0
#define MODE_QREL  2
#define MODE_Q     3
#define MODE_KV    4

// ---------------- device scratch ----------------
__device__ __align__(16) float g_qrel[BH * L_SEQ * QRP];
__device__ __align__(16) __nv_bfloat16 g_Qh[BH * L_SEQ * HD];
__device__ __align__(16) __nv_bfloat16 g_Ql[BH * L_SEQ * HD];
__device__ __align__(16) __half g_Qf[BH * L_SEQ * HD];
__device__ __align__(16) __half g_Kf[BH * L_SEQ * HD];
__device__ __align__(16) __half g_Vf[BH * L_SEQ * HD];
__device__ __align__(16) __nv_bfloat16 g_Ah[MROWS * DM];
__device__ __align__(16) __nv_bfloat16 g_Al[MROWS * DM];
__device__ __align__(16) __nv_bfloat16 g_Bh[DM * DM];
__device__ __align__(16) __nv_bfloat16 g_Bl[DM * DM];

// ---------------- helpers ----------------
static __device__ __forceinline__ uint32_t smem_u32(const void* p) {
    uint32_t a;
    asm("{ .reg .u64 t; cvta.to.shared.u64 t, %1; cvt.u32.u64 %0, t; }" : "=r"(a) : "l"(p));
    return a;
}
static __device__ __forceinline__ uint32_t swz(uint32_t b) { return b ^ ((b >> 3) & 0x70); }

static __device__ __forceinline__ void ldmx4(uint32_t* r, uint32_t addr) {
    asm volatile("ldmatrix.sync.aligned.m8n8.x4.shared.b16 {%0,%1,%2,%3}, [%4];"
                 : "=r"(r[0]), "=r"(r[1]), "=r"(r[2]), "=r"(r[3]) : "r"(addr));
}
static __device__ __forceinline__ void ldmx4t(uint32_t* r, uint32_t addr) {
    asm volatile("ldmatrix.sync.aligned.m8n8.x4.trans.shared.b16 {%0,%1,%2,%3}, [%4];"
                 : "=r"(r[0]), "=r"(r[1]), "=r"(r[2]), "=r"(r[3]) : "r"(addr));
}
static __device__ __forceinline__ void mma_bf16(float* c, const uint32_t* a, const uint32_t* b) {
    asm volatile("mma.sync.aligned.m16n8k16.row.col.f32.bf16.bf16.f32 "
                 "{%0,%1,%2,%3}, {%4,%5,%6,%7}, {%8,%9}, {%0,%1,%2,%3};"
                 : "+f"(c[0]), "+f"(c[1]), "+f"(c[2]), "+f"(c[3])
                 : "r"(a[0]), "r"(a[1]), "r"(a[2]), "r"(a[3]), "r"(b[0]), "r"(b[1]));
}
static __device__ __forceinline__ void mma_f16(float* c, const uint32_t* a, const uint32_t* b) {
    asm volatile("mma.sync.aligned.m16n8k16.row.col.f32.f16.f16.f32 "
                 "{%0,%1,%2,%3}, {%4,%5,%6,%7}, {%8,%9}, {%0,%1,%2,%3};"
                 : "+f"(c[0]), "+f"(c[1]), "+f"(c[2]), "+f"(c[3])
                 : "r"(a[0]), "r"(a[1]), "r"(a[2]), "r"(a[3]), "r"(b[0]), "r"(b[1]));
}
static __device__ __forceinline__ void cpasync16(uint32_t dst, const void* src, uint32_t ssz) {
    asm volatile("cp.async.cg.shared.global [%0], [%1], 16, %2;"
                 :: "r"(dst), "l"(src), "r"(ssz) : "memory");
}
static __device__ __forceinline__ void cp_commit() {
    asm volatile("cp.async.commit_group;" ::: "memory");
}

// ---------------- elementwise fp32 -> bf16 hi/lo split ----------------
__global__ void convert_split(const float* __restrict__ x,
                              __nv_bfloat16* __restrict__ hi,
                              __nv_bfloat16* __restrict__ lo, int n)
{
    int i = (blockIdx.x * blockDim.x + threadIdx.x) * 4;
    if (i >= n) return;
    float4 v = *(const float4*)(x + i);
    __nv_bfloat16 h0 = __float2bfloat16(v.x);
    __nv_bfloat16 h1 = __float2bfloat16(v.y);
    __nv_bfloat16 h2 = __float2bfloat16(v.z);
    __nv_bfloat16 h3 = __float2bfloat16(v.w);
    __nv_bfloat162* H = (__nv_bfloat162*)(hi + i);
    __nv_bfloat162* L = (__nv_bfloat162*)(lo + i);
    H[0] = __halves2bfloat162(h0, h1);
    H[1] = __halves2bfloat162(h2, h3);
    L[0] = __halves2bfloat162(__float2bfloat16(v.x - __bfloat162float(h0)),
                              __float2bfloat16(v.y - __bfloat162float(h1)));
    L[1] = __halves2bfloat162(__float2bfloat16(v.z - __bfloat162float(h2)),
                              __float2bfloat16(v.w - __bfloat162float(h3)));
}

// ---------------- W (KxN) -> W^T (NxK) with hi/lo split ----------------
__global__ void transpose_split(const float* __restrict__ W,
                                __nv_bfloat16* __restrict__ Th,
                                __nv_bfloat16* __restrict__ Tl)
{
    __shared__ float t[32][33];
    const int tx = threadIdx.x, ty = threadIdx.y;
    const int n = blockIdx.x * 32 + tx;
    const int k = blockIdx.y * 32 + ty;
    t[ty][tx] = W[k * DM + n];
    __syncthreads();
    const int on = blockIdx.x * 32 + ty;
    const int ok = blockIdx.y * 32 + tx;
    const float v = t[tx][ty];
    __nv_bfloat16 h = __float2bfloat16(v);
    Th[on * DM + ok] = h;
    Tl[on * DM + ok] = __float2bfloat16(v - __bfloat162float(h));
}

// =====================================================================
// HMMA GEMM: C(MxN) = A(MxK) @ B(NxK)^T + bias, split-bf16 (3 passes).
// =====================================================================
__global__ void __launch_bounds__(256) hmma_gemm(
    const __nv_bfloat16* __restrict__ Ah, const __nv_bfloat16* __restrict__ Al,
    const __nv_bfloat16* __restrict__ Bh, const __nv_bfloat16* __restrict__ Bl,
    const float* __restrict__ bias, float* __restrict__ C,
    __nv_bfloat16* __restrict__ Ch, __nv_bfloat16* __restrict__ Cl,
    __half* __restrict__ Cf,
    int M, int N, int K, int mode)
{
    extern __shared__ char smc[];
    const uint32_t sb0 = smem_u32(smc);
    const uint32_t sbuf = (sb0 + 1023u) & ~1023u;

    const int tid = threadIdx.x;
    const int wid = tid >> 5, lane = tid & 31;
    const int wm = wid & 3, wn = wid >> 2;
    const int bm = blockIdx.y << 7, bn = blockIdx.x << 7;

    float acc[2][8][4];
#pragma unroll
    for (int i = 0; i < 2; i++)
#pragma unroll
        for (int j = 0; j < 8; j++)
#pragma unroll
            for (int k = 0; k < 4; k++) acc[i][j][k] = 0.f;

    const int nc = K >> 6;

    auto issue_chunk = [&](int c) {
        const int k0 = c << 6;
        const uint32_t bufb = sbuf + (uint32_t)(c & 1) * 65536u;
#pragma unroll
        for (int t = 0; t < 4; t++) {
            const int u = tid + (t << 8);
            const int row = u >> 3, i = u & 7;
            const uint32_t so = swz((uint32_t)(row * 128 + i * 16));
            const size_t aoff = (((size_t)(bm + row) * K + k0) >> 3) + i;
            cpasync16(bufb + so,          (const uint4*)Ah + aoff, 16u);
            cpasync16(bufb + 16384u + so, (const uint4*)Al + aoff, 16u);
            const int nr = bn + row;
            const size_t boff = (((size_t)nr * K + k0) >> 3) + i;
            const uint32_t bsz = (nr < N) ? 16u : 0u;
            cpasync16(bufb + 32768u + so, (const uint4*)Bh + boff, bsz);
            cpasync16(bufb + 49152u + so, (const uint4*)Bl + boff, bsz);
        }
        cp_commit();
    };

    issue_chunk(0);
    if (nc > 1) issue_chunk(1);

    for (int c = 0; c < nc; c++) {
        if (c + 1 < nc) {
            asm volatile("cp.async.wait_group 1;" ::: "memory");
        } else {
            asm volatile("cp.async.wait_group 0;" ::: "memory");
        }
        __syncthreads();

        const uint32_t bufb = sbuf + (uint32_t)(c & 1) * 65536u;
#pragma unroll
        for (int kk = 0; kk < 4; kk++) {
            const uint32_t kb = (uint32_t)(kk << 5);
            uint32_t ah[8], al[8];
#pragma unroll
            for (int mf = 0; mf < 2; mf++) {
                const uint32_t r = (uint32_t)(wm * 32 + mf * 16 + (lane & 15));
                const uint32_t cb = kb + (uint32_t)((lane >> 4) << 4);
                const uint32_t adr = swz(r * 128 + cb);
                ldmx4(ah + mf * 4, bufb + adr);
                ldmx4(al + mf * 4, bufb + 16384u + adr);
            }
            uint32_t bh[16], bl[16];
#pragma unroll
            for (int nf2 = 0; nf2 < 4; nf2++) {
                const uint32_t r = (uint32_t)(wn * 64 + nf2 * 16 + (lane & 7) + ((lane >> 4) << 3));
                const uint32_t cb = kb + (uint32_t)(((lane >> 3) & 1) << 4);
                const uint32_t adr = swz(r * 128 + cb);
                ldmx4(bh + nf2 * 4, bufb + 32768u + adr);
                ldmx4(bl + nf2 * 4, bufb + 49152u + adr);
            }
#pragma unroll
            for (int mf = 0; mf < 2; mf++)
#pragma unroll
                for (int nf = 0; nf < 8; nf++) {
                    const int bi = (nf >> 1) * 4 + (nf & 1) * 2;
                    mma_bf16(acc[mf][nf], ah + mf * 4, bh + bi);
                    mma_bf16(acc[mf][nf], ah + mf * 4, bl + bi);
                    mma_bf16(acc[mf][nf], al + mf * 4, bh + bi);
                }
        }
        __syncthreads();
        if (c + 2 < nc) issue_chunk(c + 2);
    }

    // ---------------- epilogue ----------------
    const int gid = lane >> 2, tig = lane & 3;
#pragma unroll
    for (int mf = 0; mf < 2; mf++) {
        const int m0 = bm + wm * 32 + mf * 16 + gid;
#pragma unroll
        for (int nf = 0; nf < 8; nf++) {
            const int col = bn + wn * 64 + nf * 8 + tig * 2;
            float b0 = 0.f, b1 = 0.f;
            if (bias) { b0 = __ldg(bias + col); b1 = __ldg(bias + col + 1); }
            const float v00 = acc[mf][nf][0] + b0, v01 = acc[mf][nf][1] + b1;
            const float v10 = acc[mf][nf][2] + b0, v11 = acc[mf][nf][3] + b1;
            if (mode == MODE_Q || mode == MODE_KV) {
                const int h = col >> 6, d = col & 63;
                const int b_ = m0 >> 11, l0 = m0 & 2047;
                const size_t o0 = (((size_t)b_ * NH + h) * L_SEQ + l0) * HD + d;
                const size_t o1 = o0 + (size_t)8 * HD;
                *(__half2*)(Cf + o0) = __floats2half2_rn(v00, v01);
                *(__half2*)(Cf + o1) = __floats2half2_rn(v10, v11);
                if (mode == MODE_Q) {
                    __nv_bfloat16 h00 = __float2bfloat16(v00), h01 = __float2bfloat16(v01);
                    __nv_bfloat16 h10 = __float2bfloat16(v10), h11 = __float2bfloat16(v11);
                    *(__nv_bfloat162*)(Ch + o0) = __halves2bfloat162(h00, h01);
                    *(__nv_bfloat162*)(Ch + o1) = __halves2bfloat162(h10, h11);
                    *(__nv_bfloat162*)(Cl + o0) = __halves2bfloat162(
                        __float2bfloat16(v00 - __bfloat162float(h00)),
                        __float2bfloat16(v01 - __bfloat162float(h01)));
                    *(__nv_bfloat162*)(Cl + o1) = __halves2bfloat162(
                        __float2bfloat16(v10 - __bfloat162float(h10)),
                        __float2bfloat16(v11 - __bfloat162float(h11)));
                }
            } else if (mode == MODE_PLAIN) {
                *(float2*)(C + (size_t)m0 * N + col) = make_float2(v00, v01);
                *(float2*)(C + (size_t)(m0 + 8) * N + col) = make_float2(v10, v11);
            } else { // MODE_QREL
                if (col + 1 < N) {
                    *(float2*)(C + (size_t)m0 * QRP + col) = make_float2(v00, v01);
                    *(float2*)(C + (size_t)(m0 + 8) * QRP + col) = make_float2(v10, v11);
                } else if (col < N) {
                    C[(size_t)m0 * QRP + col] = v00;
                    C[(size_t)(m0 + 8) * QRP + col] = v10;
                }
            }
        }
    }
}

// =====================================================================
// Flash attention, single-pass fp16 HMMA.
// Grid (L/128, BH), 256 threads = 8 warps x 16 rows.
// smem: Qf 16K | Kf 16K | Vf 16K | Pf 128x272B = ~84KB
// =====================================================================
#define FLASH_SMEM_BYTES (49152 + 34816)
__global__ void __launch_bounds__(256) flash_f16()
{
    extern __shared__ char smc[];
    const uint32_t sb = smem_u32(smc);
    char* pQ = smc;          char* pK = smc + 16384;
    char* pV = smc + 32768;  char* pP = smc + 49152;
    const uint32_t uQ = sb, uK = sb + 16384, uV = sb + 32768, uP = sb + 49152;

    const int tid = threadIdx.x, w = tid >> 5, lane = tid & 31;
    const int tig = lane & 3, grp = lane >> 2;
    const int bh = blockIdx.y, i0 = blockIdx.x << 7;

    // load Q tile fp16 (rows of 128 B)
    const uint4* gQ = (const uint4*)(g_Qf + (size_t)(bh * L_SEQ + i0) * HD);
#pragma unroll
    for (int t = 0; t < 4; t++) {
        const int u = tid + (t << 8);
        const int r = u >> 3, i = u & 7;
        *(uint4*)(pQ + swz((uint32_t)(r * 128 + i * 16))) = gQ[r * 8 + i];
    }

    float O[8][4];
#pragma unroll
    for (int i = 0; i < 8; i++)
#pragma unroll
        for (int j = 0; j < 4; j++) O[i][j] = 0.f;
    float m_a = -1e30f, m_b = -1e30f, l_a = 0.f, l_b = 0.f;

    const int ia = i0 + w * 16 + grp, ib = ia + 8;
    const float* qra = g_qrel + (size_t)(bh * L_SEQ + ia) * QRP + 512;
    const float* qrb = g_qrel + (size_t)(bh * L_SEQ + ib) * QRP + 512;

    const uint4* gK = (const uint4*)(g_Kf + (size_t)bh * L_SEQ * HD);
    const uint4* gV = (const uint4*)(g_Vf + (size_t)bh * L_SEQ * HD);

    const float SCL = 0.125f * 1.4426950408889634f;

    for (int j0 = 0; j0 < L_SEQ; j0 += 128) {
        __syncthreads();
#pragma unroll
        for (int t = 0; t < 4; t++) {
            const int u = tid + (t << 8);
            const int r = u >> 3, i = u & 7;
            const uint32_t so = swz((uint32_t)(r * 128 + i * 16));
            const size_t gi = (size_t)(j0 + r) * 8 + i;
            *(uint4*)(pK + so) = gK[gi];
            *(uint4*)(pV + so) = gV[gi];
        }
        __syncthreads();

        // ---- S = QK^T (fp16 single pass) ----
        float s[16][4];
#pragma unroll
        for (int i = 0; i < 16; i++)
#pragma unroll
            for (int j = 0; j < 4; j++) s[i][j] = 0.f;

        const uint32_t ra = (uint32_t)(w * 16 + (lane & 15));
#pragma unroll
        for (int kk = 0; kk < 4; kk++) {
            const uint32_t kb = (uint32_t)(kk << 5);
            uint32_t q4[4];
            ldmx4(q4, uQ + swz(ra * 128 + kb + (uint32_t)((lane >> 4) << 4)));
#pragma unroll
            for (int g = 0; g < 8; g++) {
                const uint32_t rb = (uint32_t)(g * 16 + (lane & 7) + ((lane >> 4) << 3));
                uint32_t k4[4];
                ldmx4(k4, uK + swz(rb * 128 + kb + (uint32_t)(((lane >> 3) & 1) << 4)));
                mma_f16(s[2 * g],     q4, k4);
                mma_f16(s[2 * g + 1], q4, k4 + 2);
            }
        }

        // ---- + positional term, scale into exp2 domain ----
#pragma unroll
        for (int nf = 0; nf < 16; nf++) {
            const int j = j0 + nf * 8 + tig * 2;
            const int e0a = min(max(j - ia, -512), 512);
            const int e1a = min(max(j + 1 - ia, -512), 512);
            const int e0b = min(max(j - ib, -512), 512);
            const int e1b = min(max(j + 1 - ib, -512), 512);
            s[nf][0] = (s[nf][0] + __ldg(qra + e0a)) * SCL;
            s[nf][1] = (s[nf][1] + __ldg(qra + e1a)) * SCL;
            s[nf][2] = (s[nf][2] + __ldg(qrb + e0b)) * SCL;
            s[nf][3] = (s[nf][3] + __ldg(qrb + e1b)) * SCL;
        }

        // ---- online softmax ----
        float ma = -1e30f, mb = -1e30f;
#pragma unroll
        for (int nf = 0; nf < 16; nf++) {
            ma = fmaxf(ma, fmaxf(s[nf][0], s[nf][1]));
            mb = fmaxf(mb, fmaxf(s[nf][2], s[nf][3]));
        }
        ma = fmaxf(ma, __shfl_xor_sync(0xffffffffu, ma, 1));
        ma = fmaxf(ma, __shfl_xor_sync(0xffffffffu, ma, 2));
        mb = fmaxf(mb, __shfl_xor_sync(0xffffffffu, mb, 1));
        mb = fmaxf(mb, __shfl_xor_sync(0xffffffffu, mb, 2));
        const float mna = fmaxf(m_a, ma), mnb = fmaxf(m_b, mb);
        const float ca = exp2f(m_a - mna), cb = exp2f(m_b - mnb);
        m_a = mna; m_b = mnb;

        __syncwarp();
        char* wPa = pP + (w * 16 + grp) * 272;
        char* wPb = wPa + 8 * 272;
        float sa = 0.f, sb2 = 0.f;
#pragma unroll
        for (int nf = 0; nf < 16; nf++) {
            const float p0 = exp2f(s[nf][0] - m_a);
            const float p1 = exp2f(s[nf][1] - m_a);
            const float p2 = exp2f(s[nf][2] - m_b);
            const float p3 = exp2f(s[nf][3] - m_b);
            sa += p0 + p1;
            sb2 += p2 + p3;
            const int cbyte = nf * 16 + tig * 4;
            *(__half2*)(wPa + cbyte) = __floats2half2_rn(p0, p1);
            *(__half2*)(wPb + cbyte) = __floats2half2_rn(p2, p3);
        }
        sa += __shfl_xor_sync(0xffffffffu, sa, 1);
        sa += __shfl_xor_sync(0xffffffffu, sa, 2);
        sb2 += __shfl_xor_sync(0xffffffffu, sb2, 1);
        sb2 += __shfl_xor_sync(0xffffffffu, sb2, 2);
        l_a = l_a * ca + sa;
        l_b = l_b * cb + sb2;
#pragma unroll
        for (int nf2 = 0; nf2 < 8; nf2++) {
            O[nf2][0] *= ca; O[nf2][1] *= ca;
            O[nf2][2] *= cb; O[nf2][3] *= cb;
        }
        __syncwarp();

        // ---- O += P V (fp16 single pass) ----
#pragma unroll
        for (int k = 0; k < 8; k++) {
            const uint32_t kb = (uint32_t)(k << 5);
            uint32_t p4[4];
            ldmx4(p4, uP + (uint32_t)((w * 16 + (lane & 15)) * 272 + kb + ((lane >> 4) << 4)));
#pragma unroll
            for (int g = 0; g < 4; g++) {
                const uint32_t rv = (uint32_t)(k * 16 + (lane & 7) + (((lane >> 3) & 1) << 3));
                uint32_t v4[4];
                ldmx4t(v4, uV + swz(rv * 128 + (uint32_t)(g * 32) + (uint32_t)((lane >> 4) << 4)));
                mma_f16(O[2 * g],     p4, v4);
                mma_f16(O[2 * g + 1], p4, v4 + 2);
            }
        }
    }

    // ---- epilogue: normalize, write bf16 hi/lo merged-head ----
    const float inva = 1.f / l_a, invb = 1.f / l_b;
    const int b_ = bh >> 4, h = bh & 15;
    const size_t rowa = (size_t)b_ * L_SEQ + (i0 + w * 16 + grp);
    const size_t rowb = rowa + 8;
#pragma unroll
    for (int nf2 = 0; nf2 < 8; nf2++) {
        const int col = h * 64 + nf2 * 8 + tig * 2;
        const float v0 = O[nf2][0] * inva, v1 = O[nf2][1] * inva;
        const float v2 = O[nf2][2] * invb, v3 = O[nf2][3] * invb;
        __nv_bfloat16 h0 = __float2bfloat16(v0), h1 = __float2bfloat16(v1);
        __nv_bfloat16 h2 = __float2bfloat16(v2), h3 = __float2bfloat16(v3);
        *(__nv_bfloat162*)(g_Ah + rowa * DM + col) = __halves2bfloat162(h0, h1);
        *(__nv_bfloat162*)(g_Ah + rowb * DM + col) = __halves2bfloat162(h2, h3);
        *(__nv_bfloat162*)(g_Al + rowa * DM + col) = __halves2bfloat162(
            __float2bfloat16(v0 - __bfloat162float(h0)),
            __float2bfloat16(v1 - __bfloat162float(h1)));
        *(__nv_bfloat162*)(g_Al + rowb * DM + col) = __halves2bfloat162(
            __float2bfloat16(v2 - __bfloat162float(h2)),
            __float2bfloat16(v3 - __bfloat162float(h3)));
    }
}

// =====================================================================
extern "C" void kernel_launch(void* const* d_in, const int* in_sizes, int n_in,
                              void* d_out, int out_size)
{
    const float* query = (const float*)d_in[0];
    const float* key   = (const float*)d_in[1];
    const float* value = (const float*)d_in[2];
    const float* wq    = (const float*)d_in[3];
    const float* bq    = (const float*)d_in[4];
    const float* wk    = (const float*)d_in[5];
    const float* bk    = (const float*)d_in[6];
    const float* wv    = (const float*)d_in[7];
    const float* bv    = (const float*)d_in[8];
    const float* wo    = (const float*)d_in[9];
    const float* bo    = (const float*)d_in[10];
    const float* rel   = (const float*)d_in[11];

    float* pQrel;
    __nv_bfloat16 *pQh, *pQl, *pAh, *pAl, *pBh, *pBl;
    __half *pQf, *pKf, *pVf;
    cudaGetSymbolAddress((void**)&pQrel, g_qrel);
    cudaGetSymbolAddress((void**)&pQh, g_Qh);
    cudaGetSymbolAddress((void**)&pQl, g_Ql);
    cudaGetSymbolAddress((void**)&pQf, g_Qf);
    cudaGetSymbolAddress((void**)&pKf, g_Kf);
    cudaGetSymbolAddress((void**)&pVf, g_Vf);
    cudaGetSymbolAddress((void**)&pAh, g_Ah);
    cudaGetSymbolAddress((void**)&pAl, g_Al);
    cudaGetSymbolAddress((void**)&pBh, g_Bh);
    cudaGetSymbolAddress((void**)&pBl, g_Bl);

    const int GEMM_SMEM = 2 * 65536 + 1024;
    cudaFuncSetAttribute(hmma_gemm, cudaFuncAttributeMaxDynamicSharedMemorySize, GEMM_SMEM);
    cudaFuncSetAttribute(flash_f16, cudaFuncAttributeMaxDynamicSharedMemorySize, FLASH_SMEM_BYTES);

    const dim3 tpose_grid(32, 32), tpose_blk(32, 32);
    const dim3 proj_grid(8, 32);
    const int  NELEM = MROWS * DM;

    // ---- Q projection -> bf16 hi/lo (for qrel) + fp16 (for flash) ----
    transpose_split<<<tpose_grid, tpose_blk>>>(wq, pBh, pBl);
    convert_split<<<4096, 256>>>(query, pAh, pAl, NELEM);
    hmma_gemm<<<proj_grid, 256, GEMM_SMEM>>>(pAh, pAl, pBh, pBl, bq, nullptr,
                                             pQh, pQl, pQf, MROWS, DM, DM, MODE_Q);
    // ---- K projection -> fp16 ----
    transpose_split<<<tpose_grid, tpose_blk>>>(wk, pBh, pBl);
    convert_split<<<4096, 256>>>(key, pAh, pAl, NELEM);
    hmma_gemm<<<proj_grid, 256, GEMM_SMEM>>>(pAh, pAl, pBh, pBl, bk, nullptr,
                                             nullptr, nullptr, pKf, MROWS, DM, DM, MODE_KV);
    // ---- V projection -> fp16 ----
    transpose_split<<<tpose_grid, tpose_blk>>>(wv, pBh, pBl);
    convert_split<<<4096, 256>>>(value, pAh, pAl, NELEM);
    hmma_gemm<<<proj_grid, 256, GEMM_SMEM>>>(pAh, pAl, pBh, pBl, bv, nullptr,
                                             nullptr, nullptr, pVf, MROWS, DM, DM, MODE_KV);

    // ---- q_rel = Qh @ rel_emb^T (M=65536, N=1025, K=64, bf16 3-pass) ----
    convert_split<<<65, 256>>>(rel, pBh, pBl, NEMB * HD);
    hmma_gemm<<<dim3(9, 512), 256, GEMM_SMEM>>>(pQh, pQl, pBh, pBl, nullptr, pQrel,
                                                nullptr, nullptr, nullptr,
                                                BH * L_SEQ, NEMB, HD, MODE_QREL);

    // ---- attention (fp16 flash) -> g_Ah/g_Al merged-head bf16 hi/lo ----
    flash_f16<<<dim3(16, 32), 256, FLASH_SMEM_BYTES>>>();

    // ---- output projection (bf16 3-pass) ----
    transpose_split<<<tpose_grid, tpose_blk>>>(wo, pBh, pBl);
    hmma_gemm<<<proj_grid, 256, GEMM_SMEM>>>(pAh, pAl, pBh, pBl, bo, (float*)d_out,
                                             nullptr, nullptr, nullptr, MROWS, DM, DM, MODE_PLAIN);
}

// round 6
// speedup vs baseline: 4.2136x; 1.4036x over previous
#include <cuda_runtime.h>
#include <cuda_bf16.h>
#include <cuda_fp16.h>
#include <stdint.h>
#include <math.h>

// Problem constants
#define L_SEQ 2048
#define DM    1024
#define NH    16
#define HD    64
#define BH    32
#define NEMB  1025
#define QRP   1056
#define MROWS 4096

#define MODE_PLAIN  0
#define MODE_HSPLIT 1
#define MODE_QREL   2

// ---------------- device scratch ----------------
__device__ __align__(16) __half g_qrel[BH * L_SEQ * QRP];    // fp16, 138 MB
__device__ __align__(16) __half g_Qf[BH * L_SEQ * HD];
__device__ __align__(16) __half g_Kf[BH * L_SEQ * HD];
__device__ __align__(16) __half g_Vf[BH * L_SEQ * HD];
__device__ __align__(16) __half g_Af[MROWS * DM];            // activations / attn out (fp16)
__device__ __align__(16) __half g_Wh[DM * DM];
__device__ __align__(16) __half g_Wl[DM * DM];
__device__ __align__(16) __half g_Eh[NEMB * HD];
__device__ __align__(16) __half g_El[NEMB * HD];

// ---------------- helpers ----------------
static __device__ __forceinline__ uint32_t smem_u32(const void* p) {
    uint32_t a;
    asm("{ .reg .u64 t; cvta.to.shared.u64 t, %1; cvt.u32.u64 %0, t; }" : "=r"(a) : "l"(p));
    return a;
}
static __device__ __forceinline__ uint32_t swz(uint32_t b) { return b ^ ((b >> 3) & 0x70); }

static __device__ __forceinline__ void ldmx4(uint32_t* r, uint32_t addr) {
    asm volatile("ldmatrix.sync.aligned.m8n8.x4.shared.b16 {%0,%1,%2,%3}, [%4];"
                 : "=r"(r[0]), "=r"(r[1]), "=r"(r[2]), "=r"(r[3]) : "r"(addr));
}
static __device__ __forceinline__ void ldmx4t(uint32_t* r, uint32_t addr) {
    asm volatile("ldmatrix.sync.aligned.m8n8.x4.trans.shared.b16 {%0,%1,%2,%3}, [%4];"
                 : "=r"(r[0]), "=r"(r[1]), "=r"(r[2]), "=r"(r[3]) : "r"(addr));
}
static __device__ __forceinline__ void mma_f16(float* c, const uint32_t* a, const uint32_t* b) {
    asm volatile("mma.sync.aligned.m16n8k16.row.col.f32.f16.f16.f32 "
                 "{%0,%1,%2,%3}, {%4,%5,%6,%7}, {%8,%9}, {%0,%1,%2,%3};"
                 : "+f"(c[0]), "+f"(c[1]), "+f"(c[2]), "+f"(c[3])
                 : "r"(a[0]), "r"(a[1]), "r"(a[2]), "r"(a[3]), "r"(b[0]), "r"(b[1]));
}
static __device__ __forceinline__ void cpasync16(uint32_t dst, const void* src, uint32_t ssz) {
    asm volatile("cp.async.cg.shared.global [%0], [%1], 16, %2;"
                 :: "r"(dst), "l"(src), "r"(ssz) : "memory");
}
static __device__ __forceinline__ void cp_commit() {
    asm volatile("cp.async.commit_group;" ::: "memory");
}

// ---------------- fp32 -> fp16 ----------------
__global__ void convert_f16(const float* __restrict__ x, __half* __restrict__ y, int n)
{
    int i = (blockIdx.x * blockDim.x + threadIdx.x) * 4;
    if (i >= n) return;
    float4 v = *(const float4*)(x + i);
    __half2* Y = (__half2*)(y + i);
    Y[0] = __floats2half2_rn(v.x, v.y);
    Y[1] = __floats2half2_rn(v.z, v.w);
}

// ---------------- fp32 -> fp16 hi/lo split (no transpose) ----------------
__global__ void convert_split_f16(const float* __restrict__ x,
                                  __half* __restrict__ hi, __half* __restrict__ lo, int n)
{
    int i = (blockIdx.x * blockDim.x + threadIdx.x) * 4;
    if (i >= n) return;
    float4 v = *(const float4*)(x + i);
    __half h0 = __float2half_rn(v.x), h1 = __float2half_rn(v.y);
    __half h2 = __float2half_rn(v.z), h3 = __float2half_rn(v.w);
    __half2* H = (__half2*)(hi + i);
    __half2* L = (__half2*)(lo + i);
    H[0] = __halves2half2(h0, h1);
    H[1] = __halves2half2(h2, h3);
    L[0] = __halves2half2(__float2half_rn(v.x - __half2float(h0)),
                          __float2half_rn(v.y - __half2float(h1)));
    L[1] = __halves2half2(__float2half_rn(v.z - __half2float(h2)),
                          __float2half_rn(v.w - __half2float(h3)));
}

// ---------------- W (KxN) -> W^T (NxK) with fp16 hi/lo split ----------------
__global__ void transpose_split(const float* __restrict__ W,
                                __half* __restrict__ Th, __half* __restrict__ Tl)
{
    __shared__ float t[32][33];
    const int tx = threadIdx.x, ty = threadIdx.y;
    const int n = blockIdx.x * 32 + tx;
    const int k = blockIdx.y * 32 + ty;
    t[ty][tx] = W[k * DM + n];
    __syncthreads();
    const int on = blockIdx.x * 32 + ty;
    const int ok = blockIdx.y * 32 + tx;
    const float v = t[tx][ty];
    __half h = __float2half_rn(v);
    Th[on * DM + ok] = h;
    Tl[on * DM + ok] = __float2half_rn(v - __half2float(h));
}

// =====================================================================
// 2-pass fp16 HMMA GEMM: C = A(MxK,fp16) @ (Bh+Bl)(NxK,fp16)^T + bias.
// 128x128 CTA tile, BK=64, 256 threads, double-buffered cp.async.
// smem/chunk: A 16K | Bh 16K | Bl 16K (stride 49152, x2 buffers)
// =====================================================================
__global__ void __launch_bounds__(256) hmma_gemm2(
    const __half* __restrict__ A,
    const __half* __restrict__ Bh, const __half* __restrict__ Bl,
    const float* __restrict__ bias, float* __restrict__ C,
    __half* __restrict__ Cf,
    int M, int N, int K, int mode)
{
    extern __shared__ char smc[];
    const uint32_t sb0 = smem_u32(smc);
    const uint32_t sbuf = (sb0 + 1023u) & ~1023u;

    const int tid = threadIdx.x;
    const int wid = tid >> 5, lane = tid & 31;
    const int wm = wid & 3, wn = wid >> 2;
    const int bm = blockIdx.y << 7, bn = blockIdx.x << 7;

    float acc[2][8][4];
#pragma unroll
    for (int i = 0; i < 2; i++)
#pragma unroll
        for (int j = 0; j < 8; j++)
#pragma unroll
            for (int k = 0; k < 4; k++) acc[i][j][k] = 0.f;

    const int nc = K >> 6;

    auto issue_chunk = [&](int c) {
        const int k0 = c << 6;
        const uint32_t bufb = sbuf + (uint32_t)(c & 1) * 49152u;
#pragma unroll
        for (int t = 0; t < 4; t++) {
            const int u = tid + (t << 8);
            const int row = u >> 3, i = u & 7;
            const uint32_t so = swz((uint32_t)(row * 128 + i * 16));
            const size_t aoff = (((size_t)(bm + row) * K + k0) >> 3) + i;
            cpasync16(bufb + so, (const uint4*)A + aoff, 16u);
            const int nr = bn + row;
            const size_t boff = (((size_t)nr * K + k0) >> 3) + i;
            const uint32_t bsz = (nr < N) ? 16u : 0u;
            cpasync16(bufb + 16384u + so, (const uint4*)Bh + boff, bsz);
            cpasync16(bufb + 32768u + so, (const uint4*)Bl + boff, bsz);
        }
        cp_commit();
    };

    issue_chunk(0);
    if (nc > 1) issue_chunk(1);

    for (int c = 0; c < nc; c++) {
        if (c + 1 < nc) {
            asm volatile("cp.async.wait_group 1;" ::: "memory");
        } else {
            asm volatile("cp.async.wait_group 0;" ::: "memory");
        }
        __syncthreads();

        const uint32_t bufb = sbuf + (uint32_t)(c & 1) * 49152u;
#pragma unroll
        for (int kk = 0; kk < 4; kk++) {
            const uint32_t kb = (uint32_t)(kk << 5);
            uint32_t a4[8];
#pragma unroll
            for (int mf = 0; mf < 2; mf++) {
                const uint32_t r = (uint32_t)(wm * 32 + mf * 16 + (lane & 15));
                const uint32_t adr = swz(r * 128 + kb + (uint32_t)((lane >> 4) << 4));
                ldmx4(a4 + mf * 4, bufb + adr);
            }
            uint32_t bh[16], bl[16];
#pragma unroll
            for (int nf2 = 0; nf2 < 4; nf2++) {
                const uint32_t r = (uint32_t)(wn * 64 + nf2 * 16 + (lane & 7) + ((lane >> 4) << 3));
                const uint32_t adr = swz(r * 128 + kb + (uint32_t)(((lane >> 3) & 1) << 4));
                ldmx4(bh + nf2 * 4, bufb + 16384u + adr);
                ldmx4(bl + nf2 * 4, bufb + 32768u + adr);
            }
#pragma unroll
            for (int mf = 0; mf < 2; mf++)
#pragma unroll
                for (int nf = 0; nf < 8; nf++) {
                    const int bi = (nf >> 1) * 4 + (nf & 1) * 2;
                    mma_f16(acc[mf][nf], a4 + mf * 4, bh + bi);
                    mma_f16(acc[mf][nf], a4 + mf * 4, bl + bi);
                }
        }
        __syncthreads();
        if (c + 2 < nc) issue_chunk(c + 2);
    }

    // ---------------- epilogue ----------------
    const int gid = lane >> 2, tig = lane & 3;
#pragma unroll
    for (int mf = 0; mf < 2; mf++) {
        const int m0 = bm + wm * 32 + mf * 16 + gid;
#pragma unroll
        for (int nf = 0; nf < 8; nf++) {
            const int col = bn + wn * 64 + nf * 8 + tig * 2;
            float b0 = 0.f, b1 = 0.f;
            if (bias) { b0 = __ldg(bias + col); b1 = __ldg(bias + col + 1); }
            const float v00 = acc[mf][nf][0] + b0, v01 = acc[mf][nf][1] + b1;
            const float v10 = acc[mf][nf][2] + b0, v11 = acc[mf][nf][3] + b1;
            if (mode == MODE_HSPLIT) {
                const int h = col >> 6, d = col & 63;
                const int b_ = m0 >> 11, l0 = m0 & 2047;
                const size_t o0 = (((size_t)b_ * NH + h) * L_SEQ + l0) * HD + d;
                const size_t o1 = o0 + (size_t)8 * HD;
                *(__half2*)(Cf + o0) = __floats2half2_rn(v00, v01);
                *(__half2*)(Cf + o1) = __floats2half2_rn(v10, v11);
            } else if (mode == MODE_PLAIN) {
                *(float2*)(C + (size_t)m0 * N + col) = make_float2(v00, v01);
                *(float2*)(C + (size_t)(m0 + 8) * N + col) = make_float2(v10, v11);
            } else { // MODE_QREL: fp16 out, pitch QRP
                if (col + 1 < N) {
                    *(__half2*)(Cf + (size_t)m0 * QRP + col) = __floats2half2_rn(v00, v01);
                    *(__half2*)(Cf + (size_t)(m0 + 8) * QRP + col) = __floats2half2_rn(v10, v11);
                } else if (col < N) {
                    Cf[(size_t)m0 * QRP + col] = __float2half_rn(v00);
                    Cf[(size_t)(m0 + 8) * QRP + col] = __float2half_rn(v10);
                }
            }
        }
    }
}

// =====================================================================
// Flash attention, single-pass fp16 HMMA; fp16 qrel gather; fp16 out.
// Grid (L/128, BH), 256 threads = 8 warps x 16 rows.
// =====================================================================
#define FLASH_SMEM_BYTES (49152 + 34816)
__global__ void __launch_bounds__(256) flash_f16()
{
    extern __shared__ char smc[];
    const uint32_t sb = smem_u32(smc);
    char* pQ = smc;          char* pK = smc + 16384;
    char* pV = smc + 32768;  char* pP = smc + 49152;
    const uint32_t uQ = sb, uK = sb + 16384, uV = sb + 32768, uP = sb + 49152;

    const int tid = threadIdx.x, w = tid >> 5, lane = tid & 31;
    const int tig = lane & 3, grp = lane >> 2;
    const int bh = blockIdx.y, i0 = blockIdx.x << 7;

    const uint4* gQ = (const uint4*)(g_Qf + (size_t)(bh * L_SEQ + i0) * HD);
#pragma unroll
    for (int t = 0; t < 4; t++) {
        const int u = tid + (t << 8);
        const int r = u >> 3, i = u & 7;
        *(uint4*)(pQ + swz((uint32_t)(r * 128 + i * 16))) = gQ[r * 8 + i];
    }

    float O[8][4];
#pragma unroll
    for (int i = 0; i < 8; i++)
#pragma unroll
        for (int j = 0; j < 4; j++) O[i][j] = 0.f;
    float m_a = -1e30f, m_b = -1e30f, l_a = 0.f, l_b = 0.f;

    const int ia = i0 + w * 16 + grp, ib = ia + 8;
    const __half* qra = g_qrel + (size_t)(bh * L_SEQ + ia) * QRP + 512;
    const __half* qrb = g_qrel + (size_t)(bh * L_SEQ + ib) * QRP + 512;

    const uint4* gK = (const uint4*)(g_Kf + (size_t)bh * L_SEQ * HD);
    const uint4* gV = (const uint4*)(g_Vf + (size_t)bh * L_SEQ * HD);

    const float SCL = 0.125f * 1.4426950408889634f;

    for (int j0 = 0; j0 < L_SEQ; j0 += 128) {
        __syncthreads();
#pragma unroll
        for (int t = 0; t < 4; t++) {
            const int u = tid + (t << 8);
            const int r = u >> 3, i = u & 7;
            const uint32_t so = swz((uint32_t)(r * 128 + i * 16));
            const size_t gi = (size_t)(j0 + r) * 8 + i;
            *(uint4*)(pK + so) = gK[gi];
            *(uint4*)(pV + so) = gV[gi];
        }
        __syncthreads();

        // ---- S = QK^T ----
        float s[16][4];
#pragma unroll
        for (int i = 0; i < 16; i++)
#pragma unroll
            for (int j = 0; j < 4; j++) s[i][j] = 0.f;

        const uint32_t ra = (uint32_t)(w * 16 + (lane & 15));
#pragma unroll
        for (int kk = 0; kk < 4; kk++) {
            const uint32_t kb = (uint32_t)(kk << 5);
            uint32_t q4[4];
            ldmx4(q4, uQ + swz(ra * 128 + kb + (uint32_t)((lane >> 4) << 4)));
#pragma unroll
            for (int g = 0; g < 8; g++) {
                const uint32_t rb = (uint32_t)(g * 16 + (lane & 7) + ((lane >> 4) << 3));
                uint32_t k4[4];
                ldmx4(k4, uK + swz(rb * 128 + kb + (uint32_t)(((lane >> 3) & 1) << 4)));
                mma_f16(s[2 * g],     q4, k4);
                mma_f16(s[2 * g + 1], q4, k4 + 2);
            }
        }

        // ---- + positional term (fp16 gather), scale into exp2 domain ----
#pragma unroll
        for (int nf = 0; nf < 16; nf++) {
            const int j = j0 + nf * 8 + tig * 2;
            const int e0a = min(max(j - ia, -512), 512);
            const int e1a = min(max(j + 1 - ia, -512), 512);
            const int e0b = min(max(j - ib, -512), 512);
            const int e1b = min(max(j + 1 - ib, -512), 512);
            s[nf][0] = (s[nf][0] + __half2float(__ldg(qra + e0a))) * SCL;
            s[nf][1] = (s[nf][1] + __half2float(__ldg(qra + e1a))) * SCL;
            s[nf][2] = (s[nf][2] + __half2float(__ldg(qrb + e0b))) * SCL;
            s[nf][3] = (s[nf][3] + __half2float(__ldg(qrb + e1b))) * SCL;
        }

        // ---- online softmax ----
        float ma = -1e30f, mb = -1e30f;
#pragma unroll
        for (int nf = 0; nf < 16; nf++) {
            ma = fmaxf(ma, fmaxf(s[nf][0], s[nf][1]));
            mb = fmaxf(mb, fmaxf(s[nf][2], s[nf][3]));
        }
        ma = fmaxf(ma, __shfl_xor_sync(0xffffffffu, ma, 1));
        ma = fmaxf(ma, __shfl_xor_sync(0xffffffffu, ma, 2));
        mb = fmaxf(mb, __shfl_xor_sync(0xffffffffu, mb, 1));
        mb = fmaxf(mb, __shfl_xor_sync(0xffffffffu, mb, 2));
        const float mna = fmaxf(m_a, ma), mnb = fmaxf(m_b, mb);
        const float ca = exp2f(m_a - mna), cb = exp2f(m_b - mnb);
        m_a = mna; m_b = mnb;

        __syncwarp();
        char* wPa = pP + (w * 16 + grp) * 272;
        char* wPb = wPa + 8 * 272;
        float sa = 0.f, sb2 = 0.f;
#pragma unroll
        for (int nf = 0; nf < 16; nf++) {
            const float p0 = exp2f(s[nf][0] - m_a);
            const float p1 = exp2f(s[nf][1] - m_a);
            const float p2 = exp2f(s[nf][2] - m_b);
            const float p3 = exp2f(s[nf][3] - m_b);
            sa += p0 + p1;
            sb2 += p2 + p3;
            const int cbyte = nf * 16 + tig * 4;
            *(__half2*)(wPa + cbyte) = __floats2half2_rn(p0, p1);
            *(__half2*)(wPb + cbyte) = __floats2half2_rn(p2, p3);
        }
        sa += __shfl_xor_sync(0xffffffffu, sa, 1);
        sa += __shfl_xor_sync(0xffffffffu, sa, 2);
        sb2 += __shfl_xor_sync(0xffffffffu, sb2, 1);
        sb2 += __shfl_xor_sync(0xffffffffu, sb2, 2);
        l_a = l_a * ca + sa;
        l_b = l_b * cb + sb2;
#pragma unroll
        for (int nf2 = 0; nf2 < 8; nf2++) {
            O[nf2][0] *= ca; O[nf2][1] *= ca;
            O[nf2][2] *= cb; O[nf2][3] *= cb;
        }
        __syncwarp();

        // ---- O += P V ----
#pragma unroll
        for (int k = 0; k < 8; k++) {
            const uint32_t kb = (uint32_t)(k << 5);
            uint32_t p4[4];
            ldmx4(p4, uP + (uint32_t)((w * 16 + (lane & 15)) * 272 + kb + ((lane >> 4) << 4)));
#pragma unroll
            for (int g = 0; g < 4; g++) {
                const uint32_t rv = (uint32_t)(k * 16 + (lane & 7) + (((lane >> 3) & 1) << 3));
                uint32_t v4[4];
                ldmx4t(v4, uV + swz(rv * 128 + (uint32_t)(g * 32) + (uint32_t)((lane >> 4) << 4)));
                mma_f16(O[2 * g],     p4, v4);
                mma_f16(O[2 * g + 1], p4, v4 + 2);
            }
        }
    }

    // ---- epilogue: normalize, write fp16 merged-head ----
    const float inva = 1.f / l_a, invb = 1.f / l_b;
    const int b_ = bh >> 4, h = bh & 15;
    const size_t rowa = (size_t)b_ * L_SEQ + (i0 + w * 16 + grp);
    const size_t rowb = rowa + 8;
#pragma unroll
    for (int nf2 = 0; nf2 < 8; nf2++) {
        const int col = h * 64 + nf2 * 8 + tig * 2;
        *(__half2*)(g_Af + rowa * DM + col) = __floats2half2_rn(O[nf2][0] * inva, O[nf2][1] * inva);
        *(__half2*)(g_Af + rowb * DM + col) = __floats2half2_rn(O[nf2][2] * invb, O[nf2][3] * invb);
    }
}

// =====================================================================
extern "C" void kernel_launch(void* const* d_in, const int* in_sizes, int n_in,
                              void* d_out, int out_size)
{
    const float* query = (const float*)d_in[0];
    const float* key   = (const float*)d_in[1];
    const float* value = (const float*)d_in[2];
    const float* wq    = (const float*)d_in[3];
    const float* bq    = (const float*)d_in[4];
    const float* wk    = (const float*)d_in[5];
    const float* bk    = (const float*)d_in[6];
    const float* wv    = (const float*)d_in[7];
    const float* bv    = (const float*)d_in[8];
    const float* wo    = (const float*)d_in[9];
    const float* bo    = (const float*)d_in[10];
    const float* rel   = (const float*)d_in[11];

    __half *pQrel, *pQf, *pKf, *pVf, *pAf, *pWh, *pWl, *pEh, *pEl;
    cudaGetSymbolAddress((void**)&pQrel, g_qrel);
    cudaGetSymbolAddress((void**)&pQf, g_Qf);
    cudaGetSymbolAddress((void**)&pKf, g_Kf);
    cudaGetSymbolAddress((void**)&pVf, g_Vf);
    cudaGetSymbolAddress((void**)&pAf, g_Af);
    cudaGetSymbolAddress((void**)&pWh, g_Wh);
    cudaGetSymbolAddress((void**)&pWl, g_Wl);
    cudaGetSymbolAddress((void**)&pEh, g_Eh);
    cudaGetSymbolAddress((void**)&pEl, g_El);

    const int GEMM_SMEM = 2 * 49152 + 1024;   // 99328
    cudaFuncSetAttribute(hmma_gemm2, cudaFuncAttributeMaxDynamicSharedMemorySize, GEMM_SMEM);
    cudaFuncSetAttribute(flash_f16, cudaFuncAttributeMaxDynamicSharedMemorySize, FLASH_SMEM_BYTES);

    const dim3 tpose_grid(32, 32), tpose_blk(32, 32);
    const dim3 proj_grid(8, 32);
    const int  NELEM = MROWS * DM;

    // ---- Q projection -> fp16 head-split ----
    transpose_split<<<tpose_grid, tpose_blk>>>(wq, pWh, pWl);
    convert_f16<<<4096, 256>>>(query, pAf, NELEM);
    hmma_gemm2<<<proj_grid, 256, GEMM_SMEM>>>(pAf, pWh, pWl, bq, nullptr, pQf,
                                              MROWS, DM, DM, MODE_HSPLIT);
    // ---- K projection ----
    transpose_split<<<tpose_grid, tpose_blk>>>(wk, pWh, pWl);
    convert_f16<<<4096, 256>>>(key, pAf, NELEM);
    hmma_gemm2<<<proj_grid, 256, GEMM_SMEM>>>(pAf, pWh, pWl, bk, nullptr, pKf,
                                              MROWS, DM, DM, MODE_HSPLIT);
    // ---- V projection ----
    transpose_split<<<tpose_grid, tpose_blk>>>(wv, pWh, pWl);
    convert_f16<<<4096, 256>>>(value, pAf, NELEM);
    hmma_gemm2<<<proj_grid, 256, GEMM_SMEM>>>(pAf, pWh, pWl, bv, nullptr, pVf,
                                              MROWS, DM, DM, MODE_HSPLIT);

    // ---- q_rel = Qf @ rel^T (M=65536, N=1025, K=64) -> fp16 ----
    convert_split_f16<<<65, 256>>>(rel, pEh, pEl, NEMB * HD);
    hmma_gemm2<<<dim3(9, 512), 256, GEMM_SMEM>>>(pQf, pEh, pEl, nullptr, nullptr, pQrel,
                                                 BH * L_SEQ, NEMB, HD, MODE_QREL);

    // ---- attention ----
    flash_f16<<<dim3(16, 32), 256, FLASH_SMEM_BYTES>>>();

    // ---- output projection ----
    transpose_split<<<tpose_grid, tpose_blk>>>(wo, pWh, pWl);
    hmma_gemm2<<<proj_grid, 256, GEMM_SMEM>>>(pAf, pWh, pWl, bo, (float*)d_out, nullptr,
                                              MROWS, DM, DM, MODE_PLAIN);
}

// round 7
// speedup vs baseline: 4.2980x; 1.0200x over previous
#include <cuda_runtime.h>
#include <cuda_fp16.h>
#include <stdint.h>
#include <math.h>

// Problem constants
#define L_SEQ 2048
#define DM    1024
#define NH    16
#define HD    64
#define BH    32
#define NEMB  1025
#define QRP   1056
#define MROWS 4096
#define NELEM (MROWS * DM)

#define MODE_PLAIN  0
#define MODE_HSPLIT 1
#define MODE_QREL   2

// ---------------- device scratch ----------------
__device__ __align__(16) __half g_qrel[BH * L_SEQ * QRP];    // fp16
__device__ __align__(16) __half g_Qf[BH * L_SEQ * HD];
__device__ __align__(16) __half g_Kf[BH * L_SEQ * HD];
__device__ __align__(16) __half g_Vf[BH * L_SEQ * HD];
__device__ __align__(16) __half g_Act[3 * NELEM];            // fp16 activations (q,k,v) / attn out in slot 0
__device__ __align__(16) __half g_Wh[4 * DM * DM];           // wq,wk,wv,wo transposed hi
__device__ __align__(16) __half g_Wl[4 * DM * DM];           // lo
__device__ __align__(16) __half g_Eh[NEMB * HD];
__device__ __align__(16) __half g_El[NEMB * HD];

struct GemmBatch {
    const __half* A[3];
    const float*  bias[3];
    __half*       Cf[3];
};

// ---------------- helpers ----------------
static __device__ __forceinline__ uint32_t smem_u32(const void* p) {
    uint32_t a;
    asm("{ .reg .u64 t; cvta.to.shared.u64 t, %1; cvt.u32.u64 %0, t; }" : "=r"(a) : "l"(p));
    return a;
}
static __device__ __forceinline__ uint32_t swz(uint32_t b) { return b ^ ((b >> 3) & 0x70); }

static __device__ __forceinline__ void ldmx4(uint32_t* r, uint32_t addr) {
    asm volatile("ldmatrix.sync.aligned.m8n8.x4.shared.b16 {%0,%1,%2,%3}, [%4];"
                 : "=r"(r[0]), "=r"(r[1]), "=r"(r[2]), "=r"(r[3]) : "r"(addr));
}
static __device__ __forceinline__ void ldmx4t(uint32_t* r, uint32_t addr) {
    asm volatile("ldmatrix.sync.aligned.m8n8.x4.trans.shared.b16 {%0,%1,%2,%3}, [%4];"
                 : "=r"(r[0]), "=r"(r[1]), "=r"(r[2]), "=r"(r[3]) : "r"(addr));
}
static __device__ __forceinline__ void mma_f16(float* c, const uint32_t* a, const uint32_t* b) {
    asm volatile("mma.sync.aligned.m16n8k16.row.col.f32.f16.f16.f32 "
                 "{%0,%1,%2,%3}, {%4,%5,%6,%7}, {%8,%9}, {%0,%1,%2,%3};"
                 : "+f"(c[0]), "+f"(c[1]), "+f"(c[2]), "+f"(c[3])
                 : "r"(a[0]), "r"(a[1]), "r"(a[2]), "r"(a[3]), "r"(b[0]), "r"(b[1]));
}
static __device__ __forceinline__ void cpasync16(uint32_t dst, const void* src, uint32_t ssz) {
    asm volatile("cp.async.cg.shared.global [%0], [%1], 16, %2;"
                 :: "r"(dst), "l"(src), "r"(ssz) : "memory");
}
static __device__ __forceinline__ void cp_commit() {
    asm volatile("cp.async.commit_group;" ::: "memory");
}
static __device__ __forceinline__ uint32_t packh2(float a, float b) {
    __half2 h = __floats2half2_rn(a, b);
    return *(uint32_t*)&h;
}

// ---------------- batched fp32 -> fp16 (3 tensors) ----------------
__global__ void convert3_f16(const float* __restrict__ x0, const float* __restrict__ x1,
                             const float* __restrict__ x2)
{
    const int z = blockIdx.y;
    const float* x = (z == 0) ? x0 : (z == 1) ? x1 : x2;
    __half* y = g_Act + (size_t)z * NELEM;
    int i = (blockIdx.x * blockDim.x + threadIdx.x) * 4;
    float4 v = *(const float4*)(x + i);
    __half2* Y = (__half2*)(y + i);
    Y[0] = __floats2half2_rn(v.x, v.y);
    Y[1] = __floats2half2_rn(v.z, v.w);
}

// ---------------- fp32 -> fp16 hi/lo split (rel_emb) ----------------
__global__ void convert_split_f16(const float* __restrict__ x,
                                  __half* __restrict__ hi, __half* __restrict__ lo, int n)
{
    int i = (blockIdx.x * blockDim.x + threadIdx.x) * 4;
    if (i >= n) return;
    float4 v = *(const float4*)(x + i);
    __half h0 = __float2half_rn(v.x), h1 = __float2half_rn(v.y);
    __half h2 = __float2half_rn(v.z), h3 = __float2half_rn(v.w);
    __half2* H = (__half2*)(hi + i);
    __half2* L = (__half2*)(lo + i);
    H[0] = __halves2half2(h0, h1);
    H[1] = __halves2half2(h2, h3);
    L[0] = __halves2half2(__float2half_rn(v.x - __half2float(h0)),
                          __float2half_rn(v.y - __half2float(h1)));
    L[1] = __halves2half2(__float2half_rn(v.z - __half2float(h2)),
                          __float2half_rn(v.w - __half2float(h3)));
}

// ---------------- batched W (KxN) -> W^T (NxK) fp16 hi/lo (4 weights) ----
__global__ void transpose_split4(const float* __restrict__ w0, const float* __restrict__ w1,
                                 const float* __restrict__ w2, const float* __restrict__ w3)
{
    __shared__ float t[32][33];
    const int z = blockIdx.z;
    const float* W = (z == 0) ? w0 : (z == 1) ? w1 : (z == 2) ? w2 : w3;
    __half* Th = g_Wh + (size_t)z * DM * DM;
    __half* Tl = g_Wl + (size_t)z * DM * DM;
    const int tx = threadIdx.x, ty = threadIdx.y;
    t[ty][tx] = W[(blockIdx.y * 32 + ty) * DM + blockIdx.x * 32 + tx];
    __syncthreads();
    const int on = blockIdx.x * 32 + ty;
    const int ok = blockIdx.y * 32 + tx;
    const float v = t[tx][ty];
    __half h = __float2half_rn(v);
    Th[on * DM + ok] = h;
    Tl[on * DM + ok] = __float2half_rn(v - __half2float(h));
}

// =====================================================================
// 2-pass fp16 HMMA GEMM: C = A @ (Bh+Bl)^T + bias. Batched over grid.z.
// =====================================================================
__global__ void __launch_bounds__(256) hmma_gemm2(
    GemmBatch gb,
    const __half* __restrict__ BhBase, const __half* __restrict__ BlBase,
    float* __restrict__ C,
    int M, int N, int K, int mode)
{
    extern __shared__ char smc[];
    const uint32_t sb0 = smem_u32(smc);
    const uint32_t sbuf = (sb0 + 1023u) & ~1023u;

    const int z = blockIdx.z;
    const __half* A = gb.A[z];
    const float* bias = gb.bias[z];
    __half* Cf = gb.Cf[z];
    const __half* Bh = BhBase + (mode == MODE_HSPLIT ? (size_t)z * DM * DM : 0);
    const __half* Bl = BlBase + (mode == MODE_HSPLIT ? (size_t)z * DM * DM : 0);

    const int tid = threadIdx.x;
    const int wid = tid >> 5, lane = tid & 31;
    const int wm = wid & 3, wn = wid >> 2;
    const int bm = blockIdx.y << 7, bn = blockIdx.x << 7;

    float acc[2][8][4];
#pragma unroll
    for (int i = 0; i < 2; i++)
#pragma unroll
        for (int j = 0; j < 8; j++)
#pragma unroll
            for (int k = 0; k < 4; k++) acc[i][j][k] = 0.f;

    const int nc = K >> 6;

    auto issue_chunk = [&](int c) {
        const int k0 = c << 6;
        const uint32_t bufb = sbuf + (uint32_t)(c & 1) * 49152u;
#pragma unroll
        for (int t = 0; t < 4; t++) {
            const int u = tid + (t << 8);
            const int row = u >> 3, i = u & 7;
            const uint32_t so = swz((uint32_t)(row * 128 + i * 16));
            const size_t aoff = (((size_t)(bm + row) * K + k0) >> 3) + i;
            cpasync16(bufb + so, (const uint4*)A + aoff, 16u);
            const int nr = bn + row;
            const size_t boff = (((size_t)nr * K + k0) >> 3) + i;
            const uint32_t bsz = (nr < N) ? 16u : 0u;
            cpasync16(bufb + 16384u + so, (const uint4*)Bh + boff, bsz);
            cpasync16(bufb + 32768u + so, (const uint4*)Bl + boff, bsz);
        }
        cp_commit();
    };

    issue_chunk(0);
    if (nc > 1) issue_chunk(1);

    for (int c = 0; c < nc; c++) {
        if (c + 1 < nc) {
            asm volatile("cp.async.wait_group 1;" ::: "memory");
        } else {
            asm volatile("cp.async.wait_group 0;" ::: "memory");
        }
        __syncthreads();

        const uint32_t bufb = sbuf + (uint32_t)(c & 1) * 49152u;
#pragma unroll
        for (int kk = 0; kk < 4; kk++) {
            const uint32_t kb = (uint32_t)(kk << 5);
            uint32_t a4[8];
#pragma unroll
            for (int mf = 0; mf < 2; mf++) {
                const uint32_t r = (uint32_t)(wm * 32 + mf * 16 + (lane & 15));
                ldmx4(a4 + mf * 4, bufb + swz(r * 128 + kb + (uint32_t)((lane >> 4) << 4)));
            }
            uint32_t bh[16], bl[16];
#pragma unroll
            for (int nf2 = 0; nf2 < 4; nf2++) {
                const uint32_t r = (uint32_t)(wn * 64 + nf2 * 16 + (lane & 7) + ((lane >> 4) << 3));
                const uint32_t adr = swz(r * 128 + kb + (uint32_t)(((lane >> 3) & 1) << 4));
                ldmx4(bh + nf2 * 4, bufb + 16384u + adr);
                ldmx4(bl + nf2 * 4, bufb + 32768u + adr);
            }
#pragma unroll
            for (int mf = 0; mf < 2; mf++)
#pragma unroll
                for (int nf = 0; nf < 8; nf++) {
                    const int bi = (nf >> 1) * 4 + (nf & 1) * 2;
                    mma_f16(acc[mf][nf], a4 + mf * 4, bh + bi);
                    mma_f16(acc[mf][nf], a4 + mf * 4, bl + bi);
                }
        }
        __syncthreads();
        if (c + 2 < nc) issue_chunk(c + 2);
    }

    // ---------------- epilogue ----------------
    const int gid = lane >> 2, tig = lane & 3;
#pragma unroll
    for (int mf = 0; mf < 2; mf++) {
        const int m0 = bm + wm * 32 + mf * 16 + gid;
#pragma unroll
        for (int nf = 0; nf < 8; nf++) {
            const int col = bn + wn * 64 + nf * 8 + tig * 2;
            float b0 = 0.f, b1 = 0.f;
            if (bias) { b0 = __ldg(bias + col); b1 = __ldg(bias + col + 1); }
            const float v00 = acc[mf][nf][0] + b0, v01 = acc[mf][nf][1] + b1;
            const float v10 = acc[mf][nf][2] + b0, v11 = acc[mf][nf][3] + b1;
            if (mode == MODE_HSPLIT) {
                const int h = col >> 6, d = col & 63;
                const int b_ = m0 >> 11, l0 = m0 & 2047;
                const size_t o0 = (((size_t)b_ * NH + h) * L_SEQ + l0) * HD + d;
                const size_t o1 = o0 + (size_t)8 * HD;
                *(__half2*)(Cf + o0) = __floats2half2_rn(v00, v01);
                *(__half2*)(Cf + o1) = __floats2half2_rn(v10, v11);
            } else if (mode == MODE_PLAIN) {
                *(float2*)(C + (size_t)m0 * N + col) = make_float2(v00, v01);
                *(float2*)(C + (size_t)(m0 + 8) * N + col) = make_float2(v10, v11);
            } else { // MODE_QREL
                if (col + 1 < N) {
                    *(__half2*)(Cf + (size_t)m0 * QRP + col) = __floats2half2_rn(v00, v01);
                    *(__half2*)(Cf + (size_t)(m0 + 8) * QRP + col) = __floats2half2_rn(v10, v11);
                } else if (col < N) {
                    Cf[(size_t)m0 * QRP + col] = __float2half_rn(v00);
                    Cf[(size_t)(m0 + 8) * QRP + col] = __float2half_rn(v10);
                }
            }
        }
    }
}

// =====================================================================
// Flash attention, fp16 HMMA, register-direct P fragments (no P smem).
// Grid (L/128, BH), 256 threads. smem: Q 16K | K 16K | V 16K = 48K.
// =====================================================================
#define FLASH_SMEM_BYTES 49152
__global__ void __launch_bounds__(256) flash_f16()
{
    extern __shared__ char smc[];
    const uint32_t sb = smem_u32(smc);
    char* pQ = smc;          char* pK = smc + 16384;
    char* pV = smc + 32768;
    const uint32_t uQ = sb, uK = sb + 16384, uV = sb + 32768;

    const int tid = threadIdx.x, w = tid >> 5, lane = tid & 31;
    const int tig = lane & 3, grp = lane >> 2;
    const int bh = blockIdx.y, i0 = blockIdx.x << 7;

    const uint4* gQ = (const uint4*)(g_Qf + (size_t)(bh * L_SEQ + i0) * HD);
#pragma unroll
    for (int t = 0; t < 4; t++) {
        const int u = tid + (t << 8);
        const int r = u >> 3, i = u & 7;
        *(uint4*)(pQ + swz((uint32_t)(r * 128 + i * 16))) = gQ[r * 8 + i];
    }

    float O[8][4];
#pragma unroll
    for (int i = 0; i < 8; i++)
#pragma unroll
        for (int j = 0; j < 4; j++) O[i][j] = 0.f;
    float m_a = -1e30f, m_b = -1e30f, l_a = 0.f, l_b = 0.f;

    const int ia = i0 + w * 16 + grp, ib = ia + 8;
    const __half* qra = g_qrel + (size_t)(bh * L_SEQ + ia) * QRP + 512;
    const __half* qrb = g_qrel + (size_t)(bh * L_SEQ + ib) * QRP + 512;

    const uint4* gK = (const uint4*)(g_Kf + (size_t)bh * L_SEQ * HD);
    const uint4* gV = (const uint4*)(g_Vf + (size_t)bh * L_SEQ * HD);

    const float SCL = 0.125f * 1.4426950408889634f;

    for (int j0 = 0; j0 < L_SEQ; j0 += 128) {
        __syncthreads();
#pragma unroll
        for (int t = 0; t < 4; t++) {
            const int u = tid + (t << 8);
            const int r = u >> 3, i = u & 7;
            const uint32_t so = swz((uint32_t)(r * 128 + i * 16));
            const size_t gi = (size_t)(j0 + r) * 8 + i;
            *(uint4*)(pK + so) = gK[gi];
            *(uint4*)(pV + so) = gV[gi];
        }
        __syncthreads();

        // ---- S = QK^T ----
        float s[16][4];
#pragma unroll
        for (int i = 0; i < 16; i++)
#pragma unroll
            for (int j = 0; j < 4; j++) s[i][j] = 0.f;

        const uint32_t ra = (uint32_t)(w * 16 + (lane & 15));
#pragma unroll
        for (int kk = 0; kk < 4; kk++) {
            const uint32_t kb = (uint32_t)(kk << 5);
            uint32_t q4[4];
            ldmx4(q4, uQ + swz(ra * 128 + kb + (uint32_t)((lane >> 4) << 4)));
#pragma unroll
            for (int g = 0; g < 8; g++) {
                const uint32_t rb = (uint32_t)(g * 16 + (lane & 7) + ((lane >> 4) << 3));
                uint32_t k4[4];
                ldmx4(k4, uK + swz(rb * 128 + kb + (uint32_t)(((lane >> 3) & 1) << 4)));
                mma_f16(s[2 * g],     q4, k4);
                mma_f16(s[2 * g + 1], q4, k4 + 2);
            }
        }

        // ---- + positional term (fp16 gather), scale into exp2 domain ----
#pragma unroll
        for (int nf = 0; nf < 16; nf++) {
            const int j = j0 + nf * 8 + tig * 2;
            const int e0a = min(max(j - ia, -512), 512);
            const int e1a = min(max(j + 1 - ia, -512), 512);
            const int e0b = min(max(j - ib, -512), 512);
            const int e1b = min(max(j + 1 - ib, -512), 512);
            s[nf][0] = (s[nf][0] + __half2float(__ldg(qra + e0a))) * SCL;
            s[nf][1] = (s[nf][1] + __half2float(__ldg(qra + e1a))) * SCL;
            s[nf][2] = (s[nf][2] + __half2float(__ldg(qrb + e0b))) * SCL;
            s[nf][3] = (s[nf][3] + __half2float(__ldg(qrb + e1b))) * SCL;
        }

        // ---- online softmax ----
        float ma = -1e30f, mb = -1e30f;
#pragma unroll
        for (int nf = 0; nf < 16; nf++) {
            ma = fmaxf(ma, fmaxf(s[nf][0], s[nf][1]));
            mb = fmaxf(mb, fmaxf(s[nf][2], s[nf][3]));
        }
        ma = fmaxf(ma, __shfl_xor_sync(0xffffffffu, ma, 1));
        ma = fmaxf(ma, __shfl_xor_sync(0xffffffffu, ma, 2));
        mb = fmaxf(mb, __shfl_xor_sync(0xffffffffu, mb, 1));
        mb = fmaxf(mb, __shfl_xor_sync(0xffffffffu, mb, 2));
        const float mna = fmaxf(m_a, ma), mnb = fmaxf(m_b, mb);
        const float ca = exp2f(m_a - mna), cb = exp2f(m_b - mnb);
        m_a = mna; m_b = mnb;

        // ---- exp2 + pack P directly into MMA A-fragments ----
        uint32_t pA[16], pB[16];
        float sa = 0.f, sb2 = 0.f;
#pragma unroll
        for (int nf = 0; nf < 16; nf++) {
            const float p0 = exp2f(s[nf][0] - m_a);
            const float p1 = exp2f(s[nf][1] - m_a);
            const float p2 = exp2f(s[nf][2] - m_b);
            const float p3 = exp2f(s[nf][3] - m_b);
            sa += p0 + p1;
            sb2 += p2 + p3;
            pA[nf] = packh2(p0, p1);
            pB[nf] = packh2(p2, p3);
        }
        sa += __shfl_xor_sync(0xffffffffu, sa, 1);
        sa += __shfl_xor_sync(0xffffffffu, sa, 2);
        sb2 += __shfl_xor_sync(0xffffffffu, sb2, 1);
        sb2 += __shfl_xor_sync(0xffffffffu, sb2, 2);
        l_a = l_a * ca + sa;
        l_b = l_b * cb + sb2;
#pragma unroll
        for (int nf2 = 0; nf2 < 8; nf2++) {
            O[nf2][0] *= ca; O[nf2][1] *= ca;
            O[nf2][2] *= cb; O[nf2][3] *= cb;
        }

        // ---- O += P V (P from registers) ----
#pragma unroll
        for (int k = 0; k < 8; k++) {
            uint32_t a4[4] = { pA[2 * k], pB[2 * k], pA[2 * k + 1], pB[2 * k + 1] };
#pragma unroll
            for (int g = 0; g < 4; g++) {
                const uint32_t rv = (uint32_t)(k * 16 + (lane & 7) + (((lane >> 3) & 1) << 3));
                uint32_t v4[4];
                ldmx4t(v4, uV + swz(rv * 128 + (uint32_t)(g * 32) + (uint32_t)((lane >> 4) << 4)));
                mma_f16(O[2 * g],     a4, v4);
                mma_f16(O[2 * g + 1], a4, v4 + 2);
            }
        }
    }

    // ---- epilogue: normalize, write fp16 merged-head into g_Act slot 0 ----
    const float inva = 1.f / l_a, invb = 1.f / l_b;
    const int b_ = bh >> 4, h = bh & 15;
    const size_t rowa = (size_t)b_ * L_SEQ + (i0 + w * 16 + grp);
    const size_t rowb = rowa + 8;
#pragma unroll
    for (int nf2 = 0; nf2 < 8; nf2++) {
        const int col = h * 64 + nf2 * 8 + tig * 2;
        *(__half2*)(g_Act + rowa * DM + col) = __floats2half2_rn(O[nf2][0] * inva, O[nf2][1] * inva);
        *(__half2*)(g_Act + rowb * DM + col) = __floats2half2_rn(O[nf2][2] * invb, O[nf2][3] * invb);
    }
}

// =====================================================================
extern "C" void kernel_launch(void* const* d_in, const int* in_sizes, int n_in,
                              void* d_out, int out_size)
{
    const float* query = (const float*)d_in[0];
    const float* key   = (const float*)d_in[1];
    const float* value = (const float*)d_in[2];
    const float* wq    = (const float*)d_in[3];
    const float* bq    = (const float*)d_in[4];
    const float* wk    = (const float*)d_in[5];
    const float* bk    = (const float*)d_in[6];
    const float* wv    = (const float*)d_in[7];
    const float* bv    = (const float*)d_in[8];
    const float* wo    = (const float*)d_in[9];
    const float* bo    = (const float*)d_in[10];
    const float* rel   = (const float*)d_in[11];

    __half *pQrel, *pQf, *pKf, *pVf, *pAct, *pWh, *pWl, *pEh, *pEl;
    cudaGetSymbolAddress((void**)&pQrel, g_qrel);
    cudaGetSymbolAddress((void**)&pQf, g_Qf);
    cudaGetSymbolAddress((void**)&pKf, g_Kf);
    cudaGetSymbolAddress((void**)&pVf, g_Vf);
    cudaGetSymbolAddress((void**)&pAct, g_Act);
    cudaGetSymbolAddress((void**)&pWh, g_Wh);
    cudaGetSymbolAddress((void**)&pWl, g_Wl);
    cudaGetSymbolAddress((void**)&pEh, g_Eh);
    cudaGetSymbolAddress((void**)&pEl, g_El);

    const int GEMM_SMEM = 2 * 49152 + 1024;
    cudaFuncSetAttribute(hmma_gemm2, cudaFuncAttributeMaxDynamicSharedMemorySize, GEMM_SMEM);
    cudaFuncSetAttribute(flash_f16, cudaFuncAttributeMaxDynamicSharedMemorySize, FLASH_SMEM_BYTES);

    // ---- batched weight transposes (wq,wk,wv,wo) + input converts ----
    transpose_split4<<<dim3(32, 32, 4), dim3(32, 32)>>>(wq, wk, wv, wo);
    convert3_f16<<<dim3(4096, 3), 256>>>(query, key, value);

    // ---- batched QKV projections ----
    GemmBatch qkv;
    qkv.A[0] = pAct;            qkv.A[1] = pAct + NELEM;    qkv.A[2] = pAct + 2 * NELEM;
    qkv.bias[0] = bq;           qkv.bias[1] = bk;           qkv.bias[2] = bv;
    qkv.Cf[0] = pQf;            qkv.Cf[1] = pKf;            qkv.Cf[2] = pVf;
    hmma_gemm2<<<dim3(8, 32, 3), 256, GEMM_SMEM>>>(qkv, pWh, pWl, nullptr,
                                                   MROWS, DM, DM, MODE_HSPLIT);

    // ---- q_rel = Qf @ rel^T (M=65536, N=1025, K=64) -> fp16 ----
    convert_split_f16<<<65, 256>>>(rel, pEh, pEl, NEMB * HD);
    GemmBatch qr;
    qr.A[0] = pQf;  qr.A[1] = pQf;  qr.A[2] = pQf;
    qr.bias[0] = nullptr; qr.bias[1] = nullptr; qr.bias[2] = nullptr;
    qr.Cf[0] = pQrel; qr.Cf[1] = pQrel; qr.Cf[2] = pQrel;
    hmma_gemm2<<<dim3(9, 512, 1), 256, GEMM_SMEM>>>(qr, pEh, pEl, nullptr,
                                                    BH * L_SEQ, NEMB, HD, MODE_QREL);

    // ---- attention -> g_Act slot 0 ----
    flash_f16<<<dim3(16, 32), 256, FLASH_SMEM_BYTES>>>();

    // ---- output projection (wo = slot 3) ----
    GemmBatch op;
    op.A[0] = pAct; op.A[1] = pAct; op.A[2] = pAct;
    op.bias[0] = bo; op.bias[1] = bo; op.bias[2] = bo;
    op.Cf[0] = nullptr; op.Cf[1] = nullptr; op.Cf[2] = nullptr;
    hmma_gemm2<<<dim3(8, 32, 1), 256, GEMM_SMEM>>>(op, pWh + (size_t)3 * DM * DM,
                                                   pWl + (size_t)3 * DM * DM,
                                                   (float*)d_out, MROWS, DM, DM, MODE_PLAIN);
}

// round 8
// speedup vs baseline: 4.4413x; 1.0333x over previous
#include <cuda_runtime.h>
#include <cuda_fp16.h>
#include <stdint.h>
#include <math.h>

// Problem constants
#define L_SEQ 2048
#define DM    1024
#define NH    16
#define HD    64
#define BH    32
#define NEMB  1025
#define QRP   1056
#define MROWS 4096
#define NELEM (MROWS * DM)

#define MODE_PLAIN  0
#define MODE_HSPLIT 1
#define MODE_QREL   2

// ---------------- device scratch ----------------
__device__ __align__(16) __half g_qrel[BH * L_SEQ * QRP];
__device__ __align__(16) __half g_Qf[BH * L_SEQ * HD];
__device__ __align__(16) __half g_Kf[BH * L_SEQ * HD];
__device__ __align__(16) __half g_Vf[BH * L_SEQ * HD];
__device__ __align__(16) __half g_Act[3 * NELEM];      // q,k,v activations; slot 0 reused for attn out
__device__ __align__(16) __half g_Wh[4 * DM * DM];
__device__ __align__(16) __half g_Wl[4 * DM * DM];
__device__ __align__(16) __half g_Ef[NEMB * HD];

struct GemmBatch {
    const __half* A[3];
    const float*  bias[3];
    __half*       Cf[3];
};

// ---------------- helpers ----------------
static __device__ __forceinline__ uint32_t smem_u32(const void* p) {
    uint32_t a;
    asm("{ .reg .u64 t; cvta.to.shared.u64 t, %1; cvt.u32.u64 %0, t; }" : "=r"(a) : "l"(p));
    return a;
}
static __device__ __forceinline__ uint32_t swz(uint32_t b) { return b ^ ((b >> 3) & 0x70); }

static __device__ __forceinline__ void ldmx4(uint32_t* r, uint32_t addr) {
    asm volatile("ldmatrix.sync.aligned.m8n8.x4.shared.b16 {%0,%1,%2,%3}, [%4];"
                 : "=r"(r[0]), "=r"(r[1]), "=r"(r[2]), "=r"(r[3]) : "r"(addr));
}
static __device__ __forceinline__ void ldmx4t(uint32_t* r, uint32_t addr) {
    asm volatile("ldmatrix.sync.aligned.m8n8.x4.trans.shared.b16 {%0,%1,%2,%3}, [%4];"
                 : "=r"(r[0]), "=r"(r[1]), "=r"(r[2]), "=r"(r[3]) : "r"(addr));
}
static __device__ __forceinline__ void mma_f16(float* c, const uint32_t* a, const uint32_t* b) {
    asm volatile("mma.sync.aligned.m16n8k16.row.col.f32.f16.f16.f32 "
                 "{%0,%1,%2,%3}, {%4,%5,%6,%7}, {%8,%9}, {%0,%1,%2,%3};"
                 : "+f"(c[0]), "+f"(c[1]), "+f"(c[2]), "+f"(c[3])
                 : "r"(a[0]), "r"(a[1]), "r"(a[2]), "r"(a[3]), "r"(b[0]), "r"(b[1]));
}
static __device__ __forceinline__ void cpasync16(uint32_t dst, const void* src, uint32_t ssz) {
    asm volatile("cp.async.cg.shared.global [%0], [%1], 16, %2;"
                 :: "r"(dst), "l"(src), "r"(ssz) : "memory");
}
static __device__ __forceinline__ void cp_commit() {
    asm volatile("cp.async.commit_group;" ::: "memory");
}
static __device__ __forceinline__ uint32_t packh2(float a, float b) {
    __half2 h = __floats2half2_rn(a, b);
    return *(uint32_t*)&h;
}

// ---------------- batched fp32 -> fp16 (q,k,v inputs + rel_emb) ----------------
__global__ void convert4_f16(const float* __restrict__ x0, const float* __restrict__ x1,
                             const float* __restrict__ x2, const float* __restrict__ x3)
{
    const int z = blockIdx.y;
    if (z == 3) {
        // rel_emb: NEMB*HD = 65600 elements -> 65 blocks worth
        const int n = NEMB * HD;
        int i = (blockIdx.x * blockDim.x + threadIdx.x) * 4;
        if (i >= n) return;
        float4 v = *(const float4*)(x3 + i);
        __half2* Y = (__half2*)(g_Ef + i);
        Y[0] = __floats2half2_rn(v.x, v.y);
        Y[1] = __floats2half2_rn(v.z, v.w);
        return;
    }
    const float* x = (z == 0) ? x0 : (z == 1) ? x1 : x2;
    __half* y = g_Act + (size_t)z * NELEM;
    int i = (blockIdx.x * blockDim.x + threadIdx.x) * 4;
    float4 v = *(const float4*)(x + i);
    __half2* Y = (__half2*)(y + i);
    Y[0] = __floats2half2_rn(v.x, v.y);
    Y[1] = __floats2half2_rn(v.z, v.w);
}

// ---------------- batched W (KxN) -> W^T (NxK) fp16 hi/lo (4 weights) ----
__global__ void transpose_split4(const float* __restrict__ w0, const float* __restrict__ w1,
                                 const float* __restrict__ w2, const float* __restrict__ w3)
{
    __shared__ float t[32][33];
    const int z = blockIdx.z;
    const float* W = (z == 0) ? w0 : (z == 1) ? w1 : (z == 2) ? w2 : w3;
    __half* Th = g_Wh + (size_t)z * DM * DM;
    __half* Tl = g_Wl + (size_t)z * DM * DM;
    const int tx = threadIdx.x, ty = threadIdx.y;
    t[ty][tx] = W[(blockIdx.y * 32 + ty) * DM + blockIdx.x * 32 + tx];
    __syncthreads();
    const int on = blockIdx.x * 32 + ty;
    const int ok = blockIdx.y * 32 + tx;
    const float v = t[tx][ty];
    __half h = __float2half_rn(v);
    Th[on * DM + ok] = h;
    Tl[on * DM + ok] = __float2half_rn(v - __half2float(h));
}

// =====================================================================
// fp16 HMMA GEMM: C = A @ (Bh [+ Bl])^T + bias. twopass selects split-B.
// 128x128 CTA tile, BK=64, 256 threads, double-buffered cp.async.
// =====================================================================
__global__ void __launch_bounds__(256) hmma_gemm2(
    GemmBatch gb,
    const __half* __restrict__ BhBase, const __half* __restrict__ BlBase,
    float* __restrict__ C,
    int M, int N, int K, int mode, int twopass)
{
    extern __shared__ char smc[];
    const uint32_t sb0 = smem_u32(smc);
    const uint32_t sbuf = (sb0 + 1023u) & ~1023u;

    const int z = blockIdx.z;
    const __half* A = gb.A[z];
    const float* bias = gb.bias[z];
    __half* Cf = gb.Cf[z];
    const __half* Bh = BhBase + (mode == MODE_HSPLIT ? (size_t)z * DM * DM : 0);
    const __half* Bl = BlBase ? BlBase + (mode == MODE_HSPLIT ? (size_t)z * DM * DM : 0) : nullptr;

    const int tid = threadIdx.x;
    const int wid = tid >> 5, lane = tid & 31;
    const int wm = wid & 3, wn = wid >> 2;
    const int bm = blockIdx.y << 7, bn = blockIdx.x << 7;

    float acc[2][8][4];
#pragma unroll
    for (int i = 0; i < 2; i++)
#pragma unroll
        for (int j = 0; j < 8; j++)
#pragma unroll
            for (int k = 0; k < 4; k++) acc[i][j][k] = 0.f;

    const int nc = K >> 6;

    auto issue_chunk = [&](int c) {
        const int k0 = c << 6;
        const uint32_t bufb = sbuf + (uint32_t)(c & 1) * 49152u;
#pragma unroll
        for (int t = 0; t < 4; t++) {
            const int u = tid + (t << 8);
            const int row = u >> 3, i = u & 7;
            const uint32_t so = swz((uint32_t)(row * 128 + i * 16));
            const size_t aoff = (((size_t)(bm + row) * K + k0) >> 3) + i;
            cpasync16(bufb + so, (const uint4*)A + aoff, 16u);
            const int nr = bn + row;
            const size_t boff = (((size_t)nr * K + k0) >> 3) + i;
            const uint32_t bsz = (nr < N) ? 16u : 0u;
            cpasync16(bufb + 16384u + so, (const uint4*)Bh + boff, bsz);
            if (twopass)
                cpasync16(bufb + 32768u + so, (const uint4*)Bl + boff, bsz);
        }
        cp_commit();
    };

    issue_chunk(0);
    if (nc > 1) issue_chunk(1);

    for (int c = 0; c < nc; c++) {
        if (c + 1 < nc) {
            asm volatile("cp.async.wait_group 1;" ::: "memory");
        } else {
            asm volatile("cp.async.wait_group 0;" ::: "memory");
        }
        __syncthreads();

        const uint32_t bufb = sbuf + (uint32_t)(c & 1) * 49152u;
#pragma unroll
        for (int kk = 0; kk < 4; kk++) {
            const uint32_t kb = (uint32_t)(kk << 5);
            uint32_t a4[8];
#pragma unroll
            for (int mf = 0; mf < 2; mf++) {
                const uint32_t r = (uint32_t)(wm * 32 + mf * 16 + (lane & 15));
                ldmx4(a4 + mf * 4, bufb + swz(r * 128 + kb + (uint32_t)((lane >> 4) << 4)));
            }
            uint32_t bh[16], bl[16];
#pragma unroll
            for (int nf2 = 0; nf2 < 4; nf2++) {
                const uint32_t r = (uint32_t)(wn * 64 + nf2 * 16 + (lane & 7) + ((lane >> 4) << 3));
                const uint32_t adr = swz(r * 128 + kb + (uint32_t)(((lane >> 3) & 1) << 4));
                ldmx4(bh + nf2 * 4, bufb + 16384u + adr);
                if (twopass) ldmx4(bl + nf2 * 4, bufb + 32768u + adr);
            }
#pragma unroll
            for (int mf = 0; mf < 2; mf++)
#pragma unroll
                for (int nf = 0; nf < 8; nf++) {
                    const int bi = (nf >> 1) * 4 + (nf & 1) * 2;
                    mma_f16(acc[mf][nf], a4 + mf * 4, bh + bi);
                    if (twopass) mma_f16(acc[mf][nf], a4 + mf * 4, bl + bi);
                }
        }
        __syncthreads();
        if (c + 2 < nc) issue_chunk(c + 2);
    }

    // ---------------- epilogue ----------------
    const int gid = lane >> 2, tig = lane & 3;
#pragma unroll
    for (int mf = 0; mf < 2; mf++) {
        const int m0 = bm + wm * 32 + mf * 16 + gid;
#pragma unroll
        for (int nf = 0; nf < 8; nf++) {
            const int col = bn + wn * 64 + nf * 8 + tig * 2;
            float b0 = 0.f, b1 = 0.f;
            if (bias) { b0 = __ldg(bias + col); b1 = __ldg(bias + col + 1); }
            const float v00 = acc[mf][nf][0] + b0, v01 = acc[mf][nf][1] + b1;
            const float v10 = acc[mf][nf][2] + b0, v11 = acc[mf][nf][3] + b1;
            if (mode == MODE_HSPLIT) {
                const int h = col >> 6, d = col & 63;
                const int b_ = m0 >> 11, l0 = m0 & 2047;
                const size_t o0 = (((size_t)b_ * NH + h) * L_SEQ + l0) * HD + d;
                const size_t o1 = o0 + (size_t)8 * HD;
                *(__half2*)(Cf + o0) = __floats2half2_rn(v00, v01);
                *(__half2*)(Cf + o1) = __floats2half2_rn(v10, v11);
            } else if (mode == MODE_PLAIN) {
                *(float2*)(C + (size_t)m0 * N + col) = make_float2(v00, v01);
                *(float2*)(C + (size_t)(m0 + 8) * N + col) = make_float2(v10, v11);
            } else { // MODE_QREL
                if (col + 1 < N) {
                    *(__half2*)(Cf + (size_t)m0 * QRP + col) = __floats2half2_rn(v00, v01);
                    *(__half2*)(Cf + (size_t)(m0 + 8) * QRP + col) = __floats2half2_rn(v10, v11);
                } else if (col < N) {
                    Cf[(size_t)m0 * QRP + col] = __float2half_rn(v00);
                    Cf[(size_t)(m0 + 8) * QRP + col] = __float2half_rn(v10);
                }
            }
        }
    }
}

// =====================================================================
// Flash attention, fp16 HMMA, register P fragments, cp.async-pipelined K/V.
// Grid (L/128, BH), 256 threads. smem: Q 16K | 2 x (K 16K + V 16K) = 80K.
// =====================================================================
#define FLASH_SMEM_BYTES 81920
#define NTILES (L_SEQ / 128)
__global__ void __launch_bounds__(256) flash_f16()
{
    extern __shared__ char smc[];
    const uint32_t sb = smem_u32(smc);
    const uint32_t uQ = sb;

    const int tid = threadIdx.x, w = tid >> 5, lane = tid & 31;
    const int tig = lane & 3, grp = lane >> 2;
    const int bh = blockIdx.y, i0 = blockIdx.x << 7;

    const uint4* gQ = (const uint4*)(g_Qf + (size_t)(bh * L_SEQ + i0) * HD);
    const uint4* gK = (const uint4*)(g_Kf + (size_t)bh * L_SEQ * HD);
    const uint4* gV = (const uint4*)(g_Vf + (size_t)bh * L_SEQ * HD);

    auto issue_kv = [&](int c) {
        const uint32_t uB = sb + 16384u + (uint32_t)(c & 1) * 32768u;
#pragma unroll
        for (int t = 0; t < 4; t++) {
            const int u = tid + (t << 8);
            const int r = u >> 3, i = u & 7;
            const uint32_t so = swz((uint32_t)(r * 128 + i * 16));
            const size_t gi = (size_t)(c * 128 + r) * 8 + i;
            cpasync16(uB + so, gK + gi, 16u);
            cpasync16(uB + 16384u + so, gV + gi, 16u);
        }
        cp_commit();
    };

    // prologue: Q + KV0 as group 0, KV1 as group 1
#pragma unroll
    for (int t = 0; t < 4; t++) {
        const int u = tid + (t << 8);
        const int r = u >> 3, i = u & 7;
        cpasync16(uQ + swz((uint32_t)(r * 128 + i * 16)), gQ + r * 8 + i, 16u);
    }
    issue_kv(0);   // commits Q+KV0 together
    issue_kv(1);

    float O[8][4];
#pragma unroll
    for (int i = 0; i < 8; i++)
#pragma unroll
        for (int j = 0; j < 4; j++) O[i][j] = 0.f;
    float m_a = -1e30f, m_b = -1e30f, l_a = 0.f, l_b = 0.f;

    const int ia = i0 + w * 16 + grp, ib = ia + 8;
    const __half* qra = g_qrel + (size_t)(bh * L_SEQ + ia) * QRP + 512;
    const __half* qrb = g_qrel + (size_t)(bh * L_SEQ + ib) * QRP + 512;

    const float SCL = 0.125f * 1.4426950408889634f;

    for (int c = 0; c < NTILES; c++) {
        const int j0 = c << 7;
        if (c + 1 < NTILES) {
            asm volatile("cp.async.wait_group 1;" ::: "memory");
        } else {
            asm volatile("cp.async.wait_group 0;" ::: "memory");
        }
        __syncthreads();
        const uint32_t uK = sb + 16384u + (uint32_t)(c & 1) * 32768u;
        const uint32_t uV = uK + 16384u;

        // ---- S = QK^T ----
        float s[16][4];
#pragma unroll
        for (int i = 0; i < 16; i++)
#pragma unroll
            for (int j = 0; j < 4; j++) s[i][j] = 0.f;

        const uint32_t ra = (uint32_t)(w * 16 + (lane & 15));
#pragma unroll
        for (int kk = 0; kk < 4; kk++) {
            const uint32_t kb = (uint32_t)(kk << 5);
            uint32_t q4[4];
            ldmx4(q4, uQ + swz(ra * 128 + kb + (uint32_t)((lane >> 4) << 4)));
#pragma unroll
            for (int g = 0; g < 8; g++) {
                const uint32_t rb = (uint32_t)(g * 16 + (lane & 7) + ((lane >> 4) << 3));
                uint32_t k4[4];
                ldmx4(k4, uK + swz(rb * 128 + kb + (uint32_t)(((lane >> 3) & 1) << 4)));
                mma_f16(s[2 * g],     q4, k4);
                mma_f16(s[2 * g + 1], q4, k4 + 2);
            }
        }

        // ---- + positional term (fp16 gather), scale into exp2 domain ----
#pragma unroll
        for (int nf = 0; nf < 16; nf++) {
            const int j = j0 + nf * 8 + tig * 2;
            const int e0a = min(max(j - ia, -512), 512);
            const int e1a = min(max(j + 1 - ia, -512), 512);
            const int e0b = min(max(j - ib, -512), 512);
            const int e1b = min(max(j + 1 - ib, -512), 512);
            s[nf][0] = (s[nf][0] + __half2float(__ldg(qra + e0a))) * SCL;
            s[nf][1] = (s[nf][1] + __half2float(__ldg(qra + e1a))) * SCL;
            s[nf][2] = (s[nf][2] + __half2float(__ldg(qrb + e0b))) * SCL;
            s[nf][3] = (s[nf][3] + __half2float(__ldg(qrb + e1b))) * SCL;
        }

        // ---- online softmax ----
        float ma = -1e30f, mb = -1e30f;
#pragma unroll
        for (int nf = 0; nf < 16; nf++) {
            ma = fmaxf(ma, fmaxf(s[nf][0], s[nf][1]));
            mb = fmaxf(mb, fmaxf(s[nf][2], s[nf][3]));
        }
        ma = fmaxf(ma, __shfl_xor_sync(0xffffffffu, ma, 1));
        ma = fmaxf(ma, __shfl_xor_sync(0xffffffffu, ma, 2));
        mb = fmaxf(mb, __shfl_xor_sync(0xffffffffu, mb, 1));
        mb = fmaxf(mb, __shfl_xor_sync(0xffffffffu, mb, 2));
        const float mna = fmaxf(m_a, ma), mnb = fmaxf(m_b, mb);
        const float ca = exp2f(m_a - mna), cb = exp2f(m_b - mnb);
        m_a = mna; m_b = mnb;

        // ---- exp2 + pack P directly into MMA A-fragments ----
        uint32_t pA[16], pB[16];
        float sa = 0.f, sb2 = 0.f;
#pragma unroll
        for (int nf = 0; nf < 16; nf++) {
            const float p0 = exp2f(s[nf][0] - m_a);
            const float p1 = exp2f(s[nf][1] - m_a);
            const float p2 = exp2f(s[nf][2] - m_b);
            const float p3 = exp2f(s[nf][3] - m_b);
            sa += p0 + p1;
            sb2 += p2 + p3;
            pA[nf] = packh2(p0, p1);
            pB[nf] = packh2(p2, p3);
        }
        sa += __shfl_xor_sync(0xffffffffu, sa, 1);
        sa += __shfl_xor_sync(0xffffffffu, sa, 2);
        sb2 += __shfl_xor_sync(0xffffffffu, sb2, 1);
        sb2 += __shfl_xor_sync(0xffffffffu, sb2, 2);
        l_a = l_a * ca + sa;
        l_b = l_b * cb + sb2;
#pragma unroll
        for (int nf2 = 0; nf2 < 8; nf2++) {
            O[nf2][0] *= ca; O[nf2][1] *= ca;
            O[nf2][2] *= cb; O[nf2][3] *= cb;
        }

        // ---- O += P V (P from registers) ----
#pragma unroll
        for (int k = 0; k < 8; k++) {
            uint32_t a4[4] = { pA[2 * k], pB[2 * k], pA[2 * k + 1], pB[2 * k + 1] };
#pragma unroll
            for (int g = 0; g < 4; g++) {
                const uint32_t rv = (uint32_t)(k * 16 + (lane & 7) + (((lane >> 3) & 1) << 3));
                uint32_t v4[4];
                ldmx4t(v4, uV + swz(rv * 128 + (uint32_t)(g * 32) + (uint32_t)((lane >> 4) << 4)));
                mma_f16(O[2 * g],     a4, v4);
                mma_f16(O[2 * g + 1], a4, v4 + 2);
            }
        }
        __syncthreads();
        if (c + 2 < NTILES) issue_kv(c + 2);
    }

    // ---- epilogue: normalize, write fp16 merged-head into g_Act slot 0 ----
    const float inva = 1.f / l_a, invb = 1.f / l_b;
    const int b_ = bh >> 4, h = bh & 15;
    const size_t rowa = (size_t)b_ * L_SEQ + (i0 + w * 16 + grp);
    const size_t rowb = rowa + 8;
#pragma unroll
    for (int nf2 = 0; nf2 < 8; nf2++) {
        const int col = h * 64 + nf2 * 8 + tig * 2;
        *(__half2*)(g_Act + rowa * DM + col) = __floats2half2_rn(O[nf2][0] * inva, O[nf2][1] * inva);
        *(__half2*)(g_Act + rowb * DM + col) = __floats2half2_rn(O[nf2][2] * invb, O[nf2][3] * invb);
    }
}

// =====================================================================
extern "C" void kernel_launch(void* const* d_in, const int* in_sizes, int n_in,
                              void* d_out, int out_size)
{
    const float* query = (const float*)d_in[0];
    const float* key   = (const float*)d_in[1];
    const float* value = (const float*)d_in[2];
    const float* wq    = (const float*)d_in[3];
    const float* bq    = (const float*)d_in[4];
    const float* wk    = (const float*)d_in[5];
    const float* bk    = (const float*)d_in[6];
    const float* wv    = (const float*)d_in[7];
    const float* bv    = (const float*)d_in[8];
    const float* wo    = (const float*)d_in[9];
    const float* bo    = (const float*)d_in[10];
    const float* rel   = (const float*)d_in[11];

    __half *pQrel, *pQf, *pKf, *pVf, *pAct, *pWh, *pWl, *pEf;
    cudaGetSymbolAddress((void**)&pQrel, g_qrel);
    cudaGetSymbolAddress((void**)&pQf, g_Qf);
    cudaGetSymbolAddress((void**)&pKf, g_Kf);
    cudaGetSymbolAddress((void**)&pVf, g_Vf);
    cudaGetSymbolAddress((void**)&pAct, g_Act);
    cudaGetSymbolAddress((void**)&pWh, g_Wh);
    cudaGetSymbolAddress((void**)&pWl, g_Wl);
    cudaGetSymbolAddress((void**)&pEf, g_Ef);

    const int GEMM_SMEM = 2 * 49152 + 1024;
    cudaFuncSetAttribute(hmma_gemm2, cudaFuncAttributeMaxDynamicSharedMemorySize, GEMM_SMEM);
    cudaFuncSetAttribute(flash_f16, cudaFuncAttributeMaxDynamicSharedMemorySize, FLASH_SMEM_BYTES);

    // ---- batched weight transposes + input/rel converts ----
    transpose_split4<<<dim3(32, 32, 4), dim3(32, 32)>>>(wq, wk, wv, wo);
    convert4_f16<<<dim3(4096, 4), 256>>>(query, key, value, rel);

    // ---- batched QKV projections (2-pass split weights) ----
    GemmBatch qkv;
    qkv.A[0] = pAct;  qkv.A[1] = pAct + NELEM;  qkv.A[2] = pAct + 2 * NELEM;
    qkv.bias[0] = bq; qkv.bias[1] = bk;         qkv.bias[2] = bv;
    qkv.Cf[0] = pQf;  qkv.Cf[1] = pKf;          qkv.Cf[2] = pVf;
    hmma_gemm2<<<dim3(8, 32, 3), 256, GEMM_SMEM>>>(qkv, pWh, pWl, nullptr,
                                                   MROWS, DM, DM, MODE_HSPLIT, 1);

    // ---- q_rel = Qf @ rel^T (1-pass fp16) ----
    GemmBatch qr;
    qr.A[0] = pQf;  qr.A[1] = pQf;  qr.A[2] = pQf;
    qr.bias[0] = nullptr; qr.bias[1] = nullptr; qr.bias[2] = nullptr;
    qr.Cf[0] = pQrel; qr.Cf[1] = pQrel; qr.Cf[2] = pQrel;
    hmma_gemm2<<<dim3(9, 512, 1), 256, GEMM_SMEM>>>(qr, pEf, nullptr, nullptr,
                                                    BH * L_SEQ, NEMB, HD, MODE_QREL, 0);

    // ---- attention -> g_Act slot 0 ----
    flash_f16<<<dim3(16, 32), 256, FLASH_SMEM_BYTES>>>();

    // ---- output projection (1-pass fp16, wo = slot 3) ----
    GemmBatch op;
    op.A[0] = pAct; op.A[1] = pAct; op.A[2] = pAct;
    op.bias[0] = bo; op.bias[1] = bo; op.bias[2] = bo;
    op.Cf[0] = nullptr; op.Cf[1] = nullptr; op.Cf[2] = nullptr;
    hmma_gemm2<<<dim3(8, 32, 1), 256, GEMM_SMEM>>>(op, pWh + (size_t)3 * DM * DM, nullptr,
                                                   (float*)d_out, MROWS, DM, DM, MODE_PLAIN, 0);
}

// round 9
// speedup vs baseline: 4.4741x; 1.0074x over previous
#include <cuda_runtime.h>
#include <cuda_fp16.h>
#include <stdint.h>
#include <math.h>

// Problem constants
#define L_SEQ 2048
#define DM    1024
#define NH    16
#define HD    64
#define BH    32
#define NEMB  1025
#define QRP   1056
#define MROWS 4096
#define NELEM (MROWS * DM)

#define MODE_PLAIN  0
#define MODE_HSPLIT 1
#define MODE_QREL   2

// ---------------- device scratch ----------------
__device__ __align__(16) __half g_qrel[BH * L_SEQ * QRP];
__device__ __align__(16) __half g_Qf[BH * L_SEQ * HD];
__device__ __align__(16) __half g_Kf[BH * L_SEQ * HD];
__device__ __align__(16) __half g_Vf[BH * L_SEQ * HD];
__device__ __align__(16) __half g_Act[3 * NELEM];      // q,k,v activations; slot 0 reused for attn out
__device__ __align__(16) __half g_Wh[4 * DM * DM];
__device__ __align__(16) __half g_Wl[4 * DM * DM];
__device__ __align__(16) __half g_Ef[NEMB * HD];

struct GemmBatch {
    const __half* A[3];
    const float*  bias[3];
    __half*       Cf[3];
};

// ---------------- helpers ----------------
static __device__ __forceinline__ uint32_t smem_u32(const void* p) {
    uint32_t a;
    asm("{ .reg .u64 t; cvta.to.shared.u64 t, %1; cvt.u32.u64 %0, t; }" : "=r"(a) : "l"(p));
    return a;
}
static __device__ __forceinline__ uint32_t swz(uint32_t b) { return b ^ ((b >> 3) & 0x70); }

static __device__ __forceinline__ void ldmx4(uint32_t* r, uint32_t addr) {
    asm volatile("ldmatrix.sync.aligned.m8n8.x4.shared.b16 {%0,%1,%2,%3}, [%4];"
                 : "=r"(r[0]), "=r"(r[1]), "=r"(r[2]), "=r"(r[3]) : "r"(addr));
}
static __device__ __forceinline__ void ldmx4t(uint32_t* r, uint32_t addr) {
    asm volatile("ldmatrix.sync.aligned.m8n8.x4.trans.shared.b16 {%0,%1,%2,%3}, [%4];"
                 : "=r"(r[0]), "=r"(r[1]), "=r"(r[2]), "=r"(r[3]) : "r"(addr));
}
static __device__ __forceinline__ void mma_f16(float* c, const uint32_t* a, const uint32_t* b) {
    asm volatile("mma.sync.aligned.m16n8k16.row.col.f32.f16.f16.f32 "
                 "{%0,%1,%2,%3}, {%4,%5,%6,%7}, {%8,%9}, {%0,%1,%2,%3};"
                 : "+f"(c[0]), "+f"(c[1]), "+f"(c[2]), "+f"(c[3])
                 : "r"(a[0]), "r"(a[1]), "r"(a[2]), "r"(a[3]), "r"(b[0]), "r"(b[1]));
}
static __device__ __forceinline__ void cpasync16(uint32_t dst, const void* src, uint32_t ssz) {
    asm volatile("cp.async.cg.shared.global [%0], [%1], 16, %2;"
                 :: "r"(dst), "l"(src), "r"(ssz) : "memory");
}
static __device__ __forceinline__ void cp_commit() {
    asm volatile("cp.async.commit_group;" ::: "memory");
}
static __device__ __forceinline__ uint32_t packh2(float a, float b) {
    __half2 h = __floats2half2_rn(a, b);
    return *(uint32_t*)&h;
}

// ---------------- batched fp32 -> fp16 (q,k,v inputs + rel_emb) ----------------
__global__ void convert4_f16(const float* __restrict__ x0, const float* __restrict__ x1,
                             const float* __restrict__ x2, const float* __restrict__ x3)
{
    const int z = blockIdx.y;
    if (z == 3) {
        // rel_emb: NEMB*HD = 65600 elements -> 65 blocks worth
        const int n = NEMB * HD;
        int i = (blockIdx.x * blockDim.x + threadIdx.x) * 4;
        if (i >= n) return;
        float4 v = *(const float4*)(x3 + i);
        __half2* Y = (__half2*)(g_Ef + i);
        Y[0] = __floats2half2_rn(v.x, v.y);
        Y[1] = __floats2half2_rn(v.z, v.w);
        return;
    }
    const float* x = (z == 0) ? x0 : (z == 1) ? x1 : x2;
    __half* y = g_Act + (size_t)z * NELEM;
    int i = (blockIdx.x * blockDim.x + threadIdx.x) * 4;
    float4 v = *(const float4*)(x + i);
    __half2* Y = (__half2*)(y + i);
    Y[0] = __floats2half2_rn(v.x, v.y);
    Y[1] = __floats2half2_rn(v.z, v.w);
}

// ---------------- batched W (KxN) -> W^T (NxK) fp16 hi/lo (4 weights) ----
__global__ void transpose_split4(const float* __restrict__ w0, const float* __restrict__ w1,
                                 const float* __restrict__ w2, const float* __restrict__ w3)
{
    __shared__ float t[32][33];
    const int z = blockIdx.z;
    const float* W = (z == 0) ? w0 : (z == 1) ? w1 : (z == 2) ? w2 : w3;
    __half* Th = g_Wh + (size_t)z * DM * DM;
    __half* Tl = g_Wl + (size_t)z * DM * DM;
    const int tx = threadIdx.x, ty = threadIdx.y;
    t[ty][tx] = W[(blockIdx.y * 32 + ty) * DM + blockIdx.x * 32 + tx];
    __syncthreads();
    const int on = blockIdx.x * 32 + ty;
    const int ok = blockIdx.y * 32 + tx;
    const float v = t[tx][ty];
    __half h = __float2half_rn(v);
    Th[on * DM + ok] = h;
    Tl[on * DM + ok] = __float2half_rn(v - __half2float(h));
}

// =====================================================================
// fp16 HMMA GEMM: C = A @ (Bh [+ Bl])^T + bias. twopass selects split-B.
// 128x128 CTA tile, BK=64, 256 threads, double-buffered cp.async.
// =====================================================================
__global__ void __launch_bounds__(256) hmma_gemm2(
    GemmBatch gb,
    const __half* __restrict__ BhBase, const __half* __restrict__ BlBase,
    float* __restrict__ C,
    int M, int N, int K, int mode, int twopass)
{
    extern __shared__ char smc[];
    const uint32_t sb0 = smem_u32(smc);
    const uint32_t sbuf = (sb0 + 1023u) & ~1023u;

    const int z = blockIdx.z;
    const __half* A = gb.A[z];
    const float* bias = gb.bias[z];
    __half* Cf = gb.Cf[z];
    const __half* Bh = BhBase + (mode == MODE_HSPLIT ? (size_t)z * DM * DM : 0);
    const __half* Bl = BlBase ? BlBase + (mode == MODE_HSPLIT ? (size_t)z * DM * DM : 0) : nullptr;

    const int tid = threadIdx.x;
    const int wid = tid >> 5, lane = tid & 31;
    const int wm = wid & 3, wn = wid >> 2;
    const int bm = blockIdx.y << 7, bn = blockIdx.x << 7;

    float acc[2][8][4];
#pragma unroll
    for (int i = 0; i < 2; i++)
#pragma unroll
        for (int j = 0; j < 8; j++)
#pragma unroll
            for (int k = 0; k < 4; k++) acc[i][j][k] = 0.f;

    const int nc = K >> 6;

    auto issue_chunk = [&](int c) {
        const int k0 = c << 6;
        const uint32_t bufb = sbuf + (uint32_t)(c & 1) * 49152u;
#pragma unroll
        for (int t = 0; t < 4; t++) {
            const int u = tid + (t << 8);
            const int row = u >> 3, i = u & 7;
            const uint32_t so = swz((uint32_t)(row * 128 + i * 16));
            const size_t aoff = (((size_t)(bm + row) * K + k0) >> 3) + i;
            cpasync16(bufb + so, (const uint4*)A + aoff, 16u);
            const int nr = bn + row;
            const size_t boff = (((size_t)nr * K + k0) >> 3) + i;
            const uint32_t bsz = (nr < N) ? 16u : 0u;
            cpasync16(bufb + 16384u + so, (const uint4*)Bh + boff, bsz);
            if (twopass)
                cpasync16(bufb + 32768u + so, (const uint4*)Bl + boff, bsz);
        }
        cp_commit();
    };

    issue_chunk(0);
    if (nc > 1) issue_chunk(1);

    for (int c = 0; c < nc; c++) {
        if (c + 1 < nc) {
            asm volatile("cp.async.wait_group 1;" ::: "memory");
        } else {
            asm volatile("cp.async.wait_group 0;" ::: "memory");
        }
        __syncthreads();

        const uint32_t bufb = sbuf + (uint32_t)(c & 1) * 49152u;
#pragma unroll
        for (int kk = 0; kk < 4; kk++) {
            const uint32_t kb = (uint32_t)(kk << 5);
            uint32_t a4[8];
#pragma unroll
            for (int mf = 0; mf < 2; mf++) {
                const uint32_t r = (uint32_t)(wm * 32 + mf * 16 + (lane & 15));
                ldmx4(a4 + mf * 4, bufb + swz(r * 128 + kb + (uint32_t)((lane >> 4) << 4)));
            }
            uint32_t bh[16], bl[16];
#pragma unroll
            for (int nf2 = 0; nf2 < 4; nf2++) {
                const uint32_t r = (uint32_t)(wn * 64 + nf2 * 16 + (lane & 7) + ((lane >> 4) << 3));
                const uint32_t adr = swz(r * 128 + kb + (uint32_t)(((lane >> 3) & 1) << 4));
                ldmx4(bh + nf2 * 4, bufb + 16384u + adr);
                if (twopass) ldmx4(bl + nf2 * 4, bufb + 32768u + adr);
            }
#pragma unroll
            for (int mf = 0; mf < 2; mf++)
#pragma unroll
                for (int nf = 0; nf < 8; nf++) {
                    const int bi = (nf >> 1) * 4 + (nf & 1) * 2;
                    mma_f16(acc[mf][nf], a4 + mf * 4, bh + bi);
                    if (twopass) mma_f16(acc[mf][nf], a4 + mf * 4, bl + bi);
                }
        }
        __syncthreads();
        if (c + 2 < nc) issue_chunk(c + 2);
    }

    // ---------------- epilogue ----------------
    const int gid = lane >> 2, tig = lane & 3;
#pragma unroll
    for (int mf = 0; mf < 2; mf++) {
        const int m0 = bm + wm * 32 + mf * 16 + gid;
#pragma unroll
        for (int nf = 0; nf < 8; nf++) {
            const int col = bn + wn * 64 + nf * 8 + tig * 2;
            float b0 = 0.f, b1 = 0.f;
            if (bias) { b0 = __ldg(bias + col); b1 = __ldg(bias + col + 1); }
            const float v00 = acc[mf][nf][0] + b0, v01 = acc[mf][nf][1] + b1;
            const float v10 = acc[mf][nf][2] + b0, v11 = acc[mf][nf][3] + b1;
            if (mode == MODE_HSPLIT) {
                const int h = col >> 6, d = col & 63;
                const int b_ = m0 >> 11, l0 = m0 & 2047;
                const size_t o0 = (((size_t)b_ * NH + h) * L_SEQ + l0) * HD + d;
                const size_t o1 = o0 + (size_t)8 * HD;
                *(__half2*)(Cf + o0) = __floats2half2_rn(v00, v01);
                *(__half2*)(Cf + o1) = __floats2half2_rn(v10, v11);
            } else if (mode == MODE_PLAIN) {
                *(float2*)(C + (size_t)m0 * N + col) = make_float2(v00, v01);
                *(float2*)(C + (size_t)(m0 + 8) * N + col) = make_float2(v10, v11);
            } else { // MODE_QREL
                if (col + 1 < N) {
                    *(__half2*)(Cf + (size_t)m0 * QRP + col) = __floats2half2_rn(v00, v01);
                    *(__half2*)(Cf + (size_t)(m0 + 8) * QRP + col) = __floats2half2_rn(v10, v11);
                } else if (col < N) {
                    Cf[(size_t)m0 * QRP + col] = __float2half_rn(v00);
                    Cf[(size_t)(m0 + 8) * QRP + col] = __float2half_rn(v10);
                }
            }
        }
    }
}

// =====================================================================
// Flash attention, fp16 HMMA, register P fragments, cp.async-pipelined K/V.
// Grid (L/128, BH), 256 threads. smem: Q 16K | 2 x (K 16K + V 16K) = 80K.
// =====================================================================
#define FLASH_SMEM_BYTES 81920
#define NTILES (L_SEQ / 128)
__global__ void __launch_bounds__(256) flash_f16()
{
    extern __shared__ char smc[];
    const uint32_t sb = smem_u32(smc);
    const uint32_t uQ = sb;

    const int tid = threadIdx.x, w = tid >> 5, lane = tid & 31;
    const int tig = lane & 3, grp = lane >> 2;
    const int bh = blockIdx.y, i0 = blockIdx.x << 7;

    const uint4* gQ = (const uint4*)(g_Qf + (size_t)(bh * L_SEQ + i0) * HD);
    const uint4* gK = (const uint4*)(g_Kf + (size_t)bh * L_SEQ * HD);
    const uint4* gV = (const uint4*)(g_Vf + (size_t)bh * L_SEQ * HD);

    auto issue_kv = [&](int c) {
        const uint32_t uB = sb + 16384u + (uint32_t)(c & 1) * 32768u;
#pragma unroll
        for (int t = 0; t < 4; t++) {
            const int u = tid + (t << 8);
            const int r = u >> 3, i = u & 7;
            const uint32_t so = swz((uint32_t)(r * 128 + i * 16));
            const size_t gi = (size_t)(c * 128 + r) * 8 + i;
            cpasync16(uB + so, gK + gi, 16u);
            cpasync16(uB + 16384u + so, gV + gi, 16u);
        }
        cp_commit();
    };

    // prologue: Q + KV0 as group 0, KV1 as group 1
#pragma unroll
    for (int t = 0; t < 4; t++) {
        const int u = tid + (t << 8);
        const int r = u >> 3, i = u & 7;
        cpasync16(uQ + swz((uint32_t)(r * 128 + i * 16)), gQ + r * 8 + i, 16u);
    }
    issue_kv(0);   // commits Q+KV0 together
    issue_kv(1);

    float O[8][4];
#pragma unroll
    for (int i = 0; i < 8; i++)
#pragma unroll
        for (int j = 0; j < 4; j++) O[i][j] = 0.f;
    float m_a = -1e30f, m_b = -1e30f, l_a = 0.f, l_b = 0.f;

    const int ia = i0 + w * 16 + grp, ib = ia + 8;
    const __half* qra = g_qrel + (size_t)(bh * L_SEQ + ia) * QRP + 512;
    const __half* qrb = g_qrel + (size_t)(bh * L_SEQ + ib) * QRP + 512;

    const float SCL = 0.125f * 1.4426950408889634f;

    for (int c = 0; c < NTILES; c++) {
        const int j0 = c << 7;
        if (c + 1 < NTILES) {
            asm volatile("cp.async.wait_group 1;" ::: "memory");
        } else {
            asm volatile("cp.async.wait_group 0;" ::: "memory");
        }
        __syncthreads();
        const uint32_t uK = sb + 16384u + (uint32_t)(c & 1) * 32768u;
        const uint32_t uV = uK + 16384u;

        // ---- S = QK^T ----
        float s[16][4];
#pragma unroll
        for (int i = 0; i < 16; i++)
#pragma unroll
            for (int j = 0; j < 4; j++) s[i][j] = 0.f;

        const uint32_t ra = (uint32_t)(w * 16 + (lane & 15));
#pragma unroll
        for (int kk = 0; kk < 4; kk++) {
            const uint32_t kb = (uint32_t)(kk << 5);
            uint32_t q4[4];
            ldmx4(q4, uQ + swz(ra * 128 + kb + (uint32_t)((lane >> 4) << 4)));
#pragma unroll
            for (int g = 0; g < 8; g++) {
                const uint32_t rb = (uint32_t)(g * 16 + (lane & 7) + ((lane >> 4) << 3));
                uint32_t k4[4];
                ldmx4(k4, uK + swz(rb * 128 + kb + (uint32_t)(((lane >> 3) & 1) << 4)));
                mma_f16(s[2 * g],     q4, k4);
                mma_f16(s[2 * g + 1], q4, k4 + 2);
            }
        }

        // ---- + positional term (fp16 gather), scale into exp2 domain ----
#pragma unroll
        for (int nf = 0; nf < 16; nf++) {
            const int j = j0 + nf * 8 + tig * 2;
            const int e0a = min(max(j - ia, -512), 512);
            const int e1a = min(max(j + 1 - ia, -512), 512);
            const int e0b = min(max(j - ib, -512), 512);
            const int e1b = min(max(j + 1 - ib, -512), 512);
            s[nf][0] = (s[nf][0] + __half2float(__ldg(qra + e0a))) * SCL;
            s[nf][1] = (s[nf][1] + __half2float(__ldg(qra + e1a))) * SCL;
            s[nf][2] = (s[nf][2] + __half2float(__ldg(qrb + e0b))) * SCL;
            s[nf][3] = (s[nf][3] + __half2float(__ldg(qrb + e1b))) * SCL;
        }

        // ---- online softmax ----
        float ma = -1e30f, mb = -1e30f;
#pragma unroll
        for (int nf = 0; nf < 16; nf++) {
            ma = fmaxf(ma, fmaxf(s[nf][0], s[nf][1]));
            mb = fmaxf(mb, fmaxf(s[nf][2], s[nf][3]));
        }
        ma = fmaxf(ma, __shfl_xor_sync(0xffffffffu, ma, 1));
        ma = fmaxf(ma, __shfl_xor_sync(0xffffffffu, ma, 2));
        mb = fmaxf(mb, __shfl_xor_sync(0xffffffffu, mb, 1));
        mb = fmaxf(mb, __shfl_xor_sync(0xffffffffu, mb, 2));
        const float mna = fmaxf(m_a, ma), mnb = fmaxf(m_b, mb);
        const float ca = exp2f(m_a - mna), cb = exp2f(m_b - mnb);
        m_a = mna; m_b = mnb;

        // ---- exp2 + pack P directly into MMA A-fragments ----
        uint32_t pA[16], pB[16];
        float sa = 0.f, sb2 = 0.f;
#pragma unroll
        for (int nf = 0; nf < 16; nf++) {
            const float p0 = exp2f(s[nf][0] - m_a);
            const float p1 = exp2f(s[nf][1] - m_a);
            const float p2 = exp2f(s[nf][2] - m_b);
            const float p3 = exp2f(s[nf][3] - m_b);
            sa += p0 + p1;
            sb2 += p2 + p3;
            pA[nf] = packh2(p0, p1);
            pB[nf] = packh2(p2, p3);
        }
        sa += __shfl_xor_sync(0xffffffffu, sa, 1);
        sa += __shfl_xor_sync(0xffffffffu, sa, 2);
        sb2 += __shfl_xor_sync(0xffffffffu, sb2, 1);
        sb2 += __shfl_xor_sync(0xffffffffu, sb2, 2);
        l_a = l_a * ca + sa;
        l_b = l_b * cb + sb2;
#pragma unroll
        for (int nf2 = 0; nf2 < 8; nf2++) {
            O[nf2][0] *= ca; O[nf2][1] *= ca;
            O[nf2][2] *= cb; O[nf2][3] *= cb;
        }

        // ---- O += P V (P from registers) ----
#pragma unroll
        for (int k = 0; k < 8; k++) {
            uint32_t a4[4] = { pA[2 * k], pB[2 * k], pA[2 * k + 1], pB[2 * k + 1] };
#pragma unroll
            for (int g = 0; g < 4; g++) {
                const uint32_t rv = (uint32_t)(k * 16 + (lane & 7) + (((lane >> 3) & 1) << 3));
                uint32_t v4[4];
                ldmx4t(v4, uV + swz(rv * 128 + (uint32_t)(g * 32) + (uint32_t)((lane >> 4) << 4)));
                mma_f16(O[2 * g],     a4, v4);
                mma_f16(O[2 * g + 1], a4, v4 + 2);
            }
        }
        __syncthreads();
        if (c + 2 < NTILES) issue_kv(c + 2);
    }

    // ---- epilogue: normalize, write fp16 merged-head into g_Act slot 0 ----
    const float inva = 1.f / l_a, invb = 1.f / l_b;
    const int b_ = bh >> 4, h = bh & 15;
    const size_t rowa = (size_t)b_ * L_SEQ + (i0 + w * 16 + grp);
    const size_t rowb = rowa + 8;
#pragma unroll
    for (int nf2 = 0; nf2 < 8; nf2++) {
        const int col = h * 64 + nf2 * 8 + tig * 2;
        *(__half2*)(g_Act + rowa * DM + col) = __floats2half2_rn(O[nf2][0] * inva, O[nf2][1] * inva);
        *(__half2*)(g_Act + rowb * DM + col) = __floats2half2_rn(O[nf2][2] * invb, O[nf2][3] * invb);
    }
}

// =====================================================================
extern "C" void kernel_launch(void* const* d_in, const int* in_sizes, int n_in,
                              void* d_out, int out_size)
{
    const float* query = (const float*)d_in[0];
    const float* key   = (const float*)d_in[1];
    const float* value = (const float*)d_in[2];
    const float* wq    = (const float*)d_in[3];
    const float* bq    = (const float*)d_in[4];
    const float* wk    = (const float*)d_in[5];
    const float* bk    = (const float*)d_in[6];
    const float* wv    = (const float*)d_in[7];
    const float* bv    = (const float*)d_in[8];
    const float* wo    = (const float*)d_in[9];
    const float* bo    = (const float*)d_in[10];
    const float* rel   = (const float*)d_in[11];

    __half *pQrel, *pQf, *pKf, *pVf, *pAct, *pWh, *pWl, *pEf;
    cudaGetSymbolAddress((void**)&pQrel, g_qrel);
    cudaGetSymbolAddress((void**)&pQf, g_Qf);
    cudaGetSymbolAddress((void**)&pKf, g_Kf);
    cudaGetSymbolAddress((void**)&pVf, g_Vf);
    cudaGetSymbolAddress((void**)&pAct, g_Act);
    cudaGetSymbolAddress((void**)&pWh, g_Wh);
    cudaGetSymbolAddress((void**)&pWl, g_Wl);
    cudaGetSymbolAddress((void**)&pEf, g_Ef);

    const int GEMM_SMEM = 2 * 49152 + 1024;
    cudaFuncSetAttribute(hmma_gemm2, cudaFuncAttributeMaxDynamicSharedMemorySize, GEMM_SMEM);
    cudaFuncSetAttribute(flash_f16, cudaFuncAttributeMaxDynamicSharedMemorySize, FLASH_SMEM_BYTES);

    // ---- batched weight transposes + input/rel converts ----
    transpose_split4<<<dim3(32, 32, 4), dim3(32, 32)>>>(wq, wk, wv, wo);
    convert4_f16<<<dim3(4096, 4), 256>>>(query, key, value, rel);

    // ---- batched QKV projections (2-pass split weights) ----
    GemmBatch qkv;
    qkv.A[0] = pAct;  qkv.A[1] = pAct + NELEM;  qkv.A[2] = pAct + 2 * NELEM;
    qkv.bias[0] = bq; qkv.bias[1] = bk;         qkv.bias[2] = bv;
    qkv.Cf[0] = pQf;  qkv.Cf[1] = pKf;          qkv.Cf[2] = pVf;
    hmma_gemm2<<<dim3(8, 32, 3), 256, GEMM_SMEM>>>(qkv, pWh, pWl, nullptr,
                                                   MROWS, DM, DM, MODE_HSPLIT, 1);

    // ---- q_rel = Qf @ rel^T (1-pass fp16) ----
    GemmBatch qr;
    qr.A[0] = pQf;  qr.A[1] = pQf;  qr.A[2] = pQf;
    qr.bias[0] = nullptr; qr.bias[1] = nullptr; qr.bias[2] = nullptr;
    qr.Cf[0] = pQrel; qr.Cf[1] = pQrel; qr.Cf[2] = pQrel;
    hmma_gemm2<<<dim3(9, 512, 1), 256, GEMM_SMEM>>>(qr, pEf, nullptr, nullptr,
                                                    BH * L_SEQ, NEMB, HD, MODE_QREL, 0);

    // ---- attention -> g_Act slot 0 ----
    flash_f16<<<dim3(16, 32), 256, FLASH_SMEM_BYTES>>>();

    // ---- output projection (1-pass fp16, wo = slot 3) ----
    GemmBatch op;
    op.A[0] = pAct; op.A[1] = pAct; op.A[2] = pAct;
    op.bias[0] = bo; op.bias[1] = bo; op.bias[2] = bo;
    op.Cf[0] = nullptr; op.Cf[1] = nullptr; op.Cf[2] = nullptr;
    hmma_gemm2<<<dim3(8, 32, 1), 256, GEMM_SMEM>>>(op, pWh + (size_t)3 * DM * DM, nullptr,
                                                   (float*)d_out, MROWS, DM, DM, MODE_PLAIN, 0);
}